// round 8
// baseline (speedup 1.0000x reference)
#include <cuda_runtime.h>
#include <math.h>

#define HWSZ 16384
#define CHN  256
#define KQ   1024
#define NQ   2048
#define HSLOTS 256
#define TS 20   // transposed activation stride in floats (80B = 16B-aligned rows)

// ---------------- device scratch (static, allocation-free) ----------------
__device__ float    g_val[(size_t)2 * 4 * HWSZ * CHN];   // [b*4+f][y][x][c], +time_pos
__device__ unsigned g_keys[2 * HWSZ];
__device__ int      g_ind[NQ];
__device__ float    g_q[NQ * CHN];
__device__ float    g_qpos[NQ * CHN];
__device__ float    g_so[NQ * CHN];
__device__ float    g_aw[NQ * 128];
// interleaved by query pair: float index = (((kq>>1)*8 + h)*256 + ch)*2 + (kq&1)
__device__ float    g_agg[(size_t)NQ * 8 * CHN];
__device__ float    g_bw[NQ * 8];

// ---------------- f32x2 packed helpers ----------------
typedef unsigned long long ull;
__device__ __forceinline__ ull pk2(float x, float y) {
    ull r;
    asm("mov.b64 %0, {%1, %2};" : "=l"(r) : "f"(x), "f"(y));
    return r;
}
__device__ __forceinline__ void upk2(ull v, float& x, float& y) {
    asm("mov.b64 {%0, %1}, %2;" : "=f"(x), "=f"(y) : "l"(v));
}
__device__ __forceinline__ ull fma2(ull a, ull b, ull c) {
    ull d;
    asm("fma.rn.f32x2 %0, %1, %2, %3;" : "=l"(d) : "l"(a), "l"(b), "l"(c));
    return d;
}

__device__ __forceinline__ float gelu_tanh(float v) {
    float c = 0.7978845608028654f * (v + 0.044715f * v * v * v);
    return 0.5f * v * (1.0f + tanhf(c));
}

// ---------------- K1: transpose x[b,f,c,y,x] -> g_val[b,f,y,x,c] (+time_pos) ----------------
__global__ void k_transpose(const float* __restrict__ x, const float* __restrict__ tp) {
    __shared__ float tile[32][33];
    int xt = blockIdx.x * 32;
    int ct = blockIdx.y * 32;
    int z  = blockIdx.z;
    int y  = z & 127;
    int bf = z >> 7;
    int f  = bf & 3;
    int tx = threadIdx.x, ty = threadIdx.y;
    tile[ty][tx] = x[((size_t)(bf * CHN + ct + ty) * 128 + y) * 128 + xt + tx];
    __syncthreads();
    g_val[((size_t)(bf * 128 + y) * 128 + xt + ty) * CHN + ct + tx] =
        tile[tx][ty] + tp[f * CHN + ct + tx];
}

// ---------------- K2a: channel-max score -> orderable keys ----------------
__global__ __launch_bounds__(1024) void k_score(const float* __restrict__ hm) {
    int i = blockIdx.x * 1024 + threadIdx.x;
    int b = i >> 14, cell = i & (HWSZ - 1);
    const float* hb = hm + (size_t)b * 10 * HWSZ + cell;
    float m = hb[0];
    #pragma unroll
    for (int c = 1; c < 10; c++) m = fmaxf(m, hb[c * HWSZ]);
    unsigned u = __float_as_uint(m);
    u = (u & 0x80000000u) ? ~u : (u | 0x80000000u);
    g_keys[i] = u;
}

// ---------------- K2b: radix top-1024 per batch ----------------
__global__ __launch_bounds__(1024) void k_topk() {
    int b = blockIdx.x, t = threadIdx.x;
    __shared__ unsigned hist[256];
    __shared__ unsigned sh[4];

    unsigned prefix = 0, r = KQ;
    for (int byte = 3; byte >= 0; byte--) {
        if (t < 256) hist[t] = 0;
        __syncthreads();
        int sh8 = byte * 8;
        unsigned pm = (byte == 3) ? 0u : (0xFFFFFFFFu << (8 * (byte + 1)));
        for (int i = t; i < HWSZ; i += 1024) {
            unsigned k = g_keys[b * HWSZ + i];
            if ((k & pm) == (prefix & pm)) atomicAdd(&hist[(k >> sh8) & 255u], 1u);
        }
        __syncthreads();
        if (t == 0) {
            unsigned cum = 0, d = 0;
            for (int dd = 255; dd >= 0; dd--) {
                if (cum + hist[dd] >= r) { d = (unsigned)dd; break; }
                cum += hist[dd];
            }
            sh[0] = d; sh[1] = r - cum;
        }
        __syncthreads();
        prefix |= sh[0] << sh8;
        r = sh[1];
        __syncthreads();
    }
    unsigned T = prefix;
    if (t == 0) { sh[2] = 0; sh[3] = 0; }
    __syncthreads();
    for (int i = t; i < HWSZ; i += 1024)
        if (g_keys[b * HWSZ + i] > T) atomicAdd(&sh[2], 1u);
    __syncthreads();
    unsigned cgt = sh[2];
    unsigned neq = KQ - cgt;
    __syncthreads();
    if (t == 0) sh[2] = 0;
    __syncthreads();
    for (int i = t; i < HWSZ; i += 1024) {
        unsigned k = g_keys[b * HWSZ + i];
        if (k > T) {
            unsigned s = atomicAdd(&sh[2], 1u);
            g_ind[b * KQ + s] = i;
        } else if (k == T) {
            unsigned e = atomicAdd(&sh[3], 1u);
            if (e < neq) g_ind[b * KQ + cgt + e] = i;
        }
    }
}

// ---------------- K3: query-init MLP + positional embed gather ----------------
__global__ __launch_bounds__(256) void k_qinit(
    const float* __restrict__ preds,
    const float* __restrict__ W1, const float* __restrict__ b1,
    const float* __restrict__ W2, const float* __restrict__ b2,
    const float* __restrict__ rowe, const float* __restrict__ cole) {
    __shared__ float q0S[8][70];
    __shared__ float hidS[8][CHN];
    __shared__ int   indS[8];
    int t = threadIdx.x;
    int qg0 = blockIdx.x * 8;
    if (t < 8) indS[t] = g_ind[qg0 + t];
    __syncthreads();
    for (int idx = t; idx < 8 * 70; idx += 256) {
        int q = idx / 70, j = idx - q * 70;
        int b = (qg0 + q) >> 10;
        q0S[q][j] = preds[(b * 70 + j) * HWSZ + indS[q]];
    }
    #pragma unroll
    for (int q = 0; q < 8; q++) {
        int ind = indS[q];
        int xx = ind & 127, yy = ind >> 7;
        float pv = (t < 128) ? cole[xx * 128 + t] : rowe[yy * 128 + (t - 128)];
        g_qpos[(qg0 + q) * CHN + t] = pv;
    }
    __syncthreads();
    float acc[8] = {0.f,0.f,0.f,0.f,0.f,0.f,0.f,0.f};
    for (int j = 0; j < 70; j++) {
        float w = W1[j * CHN + t];
        #pragma unroll
        for (int q = 0; q < 8; q++) acc[q] += q0S[q][j] * w;
    }
    float bb = b1[t];
    #pragma unroll
    for (int q = 0; q < 8; q++) hidS[q][t] = gelu_tanh(acc[q] + bb);
    __syncthreads();
    float a2[8] = {0.f,0.f,0.f,0.f,0.f,0.f,0.f,0.f};
    for (int i = 0; i < CHN; i++) {
        float w = W2[i * CHN + t];
        #pragma unroll
        for (int q = 0; q < 8; q++) a2[q] += hidS[q][i] * w;
    }
    float b2v = b2[t];
    #pragma unroll
    for (int q = 0; q < 8; q++) g_q[(qg0 + q) * CHN + t] = a2[q] + b2v;
}

// ---------------- K4: so/aw GEMM + softmax, f32x2, concurrent warps (512t, Q=16) ----------------
__global__ __launch_bounds__(512) void k_soaw(
    const float* __restrict__ soW, const float* __restrict__ sob,
    const float* __restrict__ awW, const float* __restrict__ awb) {
    __shared__ __align__(16) float qnT[256 * TS];   // [i][q] transposed activations
    int t = threadIdx.x;
    int qg0 = blockIdx.x * 16;

    for (int idx = t; idx < 4096; idx += 512) {
        int q = idx & 15, i = idx >> 4;
        qnT[i * TS + q] = g_q[(qg0 + q) * CHN + i] + g_qpos[(qg0 + q) * CHN + i];
    }
    __syncthreads();

    if (t < 256) {
        ull acc2[8];
        #pragma unroll
        for (int p = 0; p < 8; p++) acc2[p] = pk2(0.f, 0.f);
        #pragma unroll 4
        for (int i = 0; i < 256; i++) {
            ull w2 = pk2(soW[i * CHN + t], soW[i * CHN + t]);
            const float4 a0 = *(const float4*)&qnT[i * TS + 0];
            const float4 a1 = *(const float4*)&qnT[i * TS + 4];
            const float4 a2_ = *(const float4*)&qnT[i * TS + 8];
            const float4 a3 = *(const float4*)&qnT[i * TS + 12];
            acc2[0] = fma2(pk2(a0.x, a0.y), w2, acc2[0]);
            acc2[1] = fma2(pk2(a0.z, a0.w), w2, acc2[1]);
            acc2[2] = fma2(pk2(a1.x, a1.y), w2, acc2[2]);
            acc2[3] = fma2(pk2(a1.z, a1.w), w2, acc2[3]);
            acc2[4] = fma2(pk2(a2_.x, a2_.y), w2, acc2[4]);
            acc2[5] = fma2(pk2(a2_.z, a2_.w), w2, acc2[5]);
            acc2[6] = fma2(pk2(a3.x, a3.y), w2, acc2[6]);
            acc2[7] = fma2(pk2(a3.z, a3.w), w2, acc2[7]);
        }
        float sbv = sob[t];
        #pragma unroll
        for (int p = 0; p < 8; p++) {
            float lo, hi;
            upk2(acc2[p], lo, hi);
            g_so[(qg0 + 2 * p) * CHN + t]     = lo + sbv;
            g_so[(qg0 + 2 * p + 1) * CHN + t] = hi + sbv;
        }
    } else if (t < 384) {
        int c = t - 256;
        ull acc2[8];
        #pragma unroll
        for (int p = 0; p < 8; p++) acc2[p] = pk2(0.f, 0.f);
        #pragma unroll 4
        for (int i = 0; i < 256; i++) {
            ull w2 = pk2(awW[i * 128 + c], awW[i * 128 + c]);
            const float4 a0 = *(const float4*)&qnT[i * TS + 0];
            const float4 a1 = *(const float4*)&qnT[i * TS + 4];
            const float4 a2_ = *(const float4*)&qnT[i * TS + 8];
            const float4 a3 = *(const float4*)&qnT[i * TS + 12];
            acc2[0] = fma2(pk2(a0.x, a0.y), w2, acc2[0]);
            acc2[1] = fma2(pk2(a0.z, a0.w), w2, acc2[1]);
            acc2[2] = fma2(pk2(a1.x, a1.y), w2, acc2[2]);
            acc2[3] = fma2(pk2(a1.z, a1.w), w2, acc2[3]);
            acc2[4] = fma2(pk2(a2_.x, a2_.y), w2, acc2[4]);
            acc2[5] = fma2(pk2(a2_.z, a2_.w), w2, acc2[5]);
            acc2[6] = fma2(pk2(a3.x, a3.y), w2, acc2[6]);
            acc2[7] = fma2(pk2(a3.z, a3.w), w2, acc2[7]);
        }
        float ab = awb[c];
        float av[16];
        #pragma unroll
        for (int p = 0; p < 8; p++) {
            upk2(acc2[p], av[2 * p], av[2 * p + 1]);
            av[2 * p] += ab; av[2 * p + 1] += ab;
        }
        #pragma unroll
        for (int q = 0; q < 16; q++) {
            float vv = av[q];
            float m = vv;
            #pragma unroll
            for (int o = 8; o > 0; o >>= 1)
                m = fmaxf(m, __shfl_xor_sync(0xffffffffu, m, o, 16));
            float e = expf(vv - m);
            float s = e;
            #pragma unroll
            for (int o = 8; o > 0; o >>= 1)
                s += __shfl_xor_sync(0xffffffffu, s, o, 16);
            g_aw[(qg0 + q) * 128 + c] = e / s;
        }
    }
}

// ---------------- K5: per-query dedup gather-aggregate (1 query / block) ----------------
__global__ __launch_bounds__(256) void k_gather() {
    __shared__ __align__(16) float hcoef[HSLOTS * 8];
    __shared__ __align__(16) float coefC[HSLOTS * 8];
    __shared__ int hkey[HSLOTS];
    __shared__ int cellList[HSLOTS];
    __shared__ int cntS;

    int t = threadIdx.x;
    int kq = blockIdx.x;
    int b = kq >> 10;

    hkey[t] = -1;
    ((float4*)hcoef)[t * 2]     = make_float4(0.f, 0.f, 0.f, 0.f);
    ((float4*)hcoef)[t * 2 + 1] = make_float4(0.f, 0.f, 0.f, 0.f);
    if (t == 0) cntS = 0;
    __syncthreads();

    if (t < 128) {
        int ind = g_ind[kq];
        int h = t >> 4;
        int f = (t >> 2) & 3;
        float offx = g_so[kq * CHN + 2 * t];
        float offy = g_so[kq * CHN + 2 * t + 1];
        float aw = g_aw[kq * 128 + t];
        float xs = (float)(ind & 127) + offx;
        float ys = (float)(ind >> 7) + offy;
        float xf = floorf(xs), yf = floorf(ys);
        int x0 = (int)xf, y0 = (int)yf;
        float wx1 = xs - xf, wy1 = ys - yf;
        float wx0 = 1.f - wx1, wy0 = 1.f - wy1;
        int cxs[4] = {x0, x0 + 1, x0, x0 + 1};
        int cys[4] = {y0, y0, y0 + 1, y0 + 1};
        float cw[4] = {wx0 * wy0, wx1 * wy0, wx0 * wy1, wx1 * wy1};
        int base = (b * 4 + f) * HWSZ;
        float evs = 0.f;
        #pragma unroll
        for (int c = 0; c < 4; c++) {
            bool v = (cxs[c] >= 0) & (cxs[c] < 128) & (cys[c] >= 0) & (cys[c] < 128);
            if (v) {
                int key = base + cys[c] * 128 + cxs[c];
                float cf = aw * cw[c];
                evs += cf;
                unsigned s = ((unsigned)key * 2654435761u) >> 24;
                while (true) {
                    int prev = atomicCAS(&hkey[s], -1, key);
                    if (prev == -1 || prev == key) break;
                    s = (s + 1) & (HSLOTS - 1);
                }
                atomicAdd(&hcoef[s * 8 + h], cf);
            }
        }
        #pragma unroll
        for (int o = 8; o > 0; o >>= 1)
            evs += __shfl_xor_sync(0xffffffffu, evs, o, 16);
        if ((t & 15) == 0) g_bw[kq * 8 + h] = evs;
    }
    __syncthreads();

    {
        int key = hkey[t];
        if (key >= 0) {
            int pos = atomicAdd(&cntS, 1);
            cellList[pos] = key;
            ((float4*)coefC)[pos * 2]     = ((const float4*)hcoef)[t * 2];
            ((float4*)coefC)[pos * 2 + 1] = ((const float4*)hcoef)[t * 2 + 1];
        }
    }
    __syncthreads();
    int D = cntS;

    // aggregate: thread = channel; f32x2, 8-wide LDG batching (MLP=8)
    ull acc2[4];
    #pragma unroll
    for (int p = 0; p < 4; p++) acc2[p] = pk2(0.f, 0.f);
    int d = 0;
    for (; d + 8 <= D; d += 8) {
        float vv[8];
        #pragma unroll
        for (int u = 0; u < 8; u++) vv[u] = g_val[(size_t)cellList[d + u] * CHN + t];
        #pragma unroll
        for (int u = 0; u < 8; u++) {
            ull v2p = pk2(vv[u], vv[u]);
            const float4 c0 = ((const float4*)coefC)[(d + u) * 2];
            const float4 c1 = ((const float4*)coefC)[(d + u) * 2 + 1];
            acc2[0] = fma2(pk2(c0.x, c0.y), v2p, acc2[0]);
            acc2[1] = fma2(pk2(c0.z, c0.w), v2p, acc2[1]);
            acc2[2] = fma2(pk2(c1.x, c1.y), v2p, acc2[2]);
            acc2[3] = fma2(pk2(c1.z, c1.w), v2p, acc2[3]);
        }
    }
    for (; d < D; d++) {
        float v = g_val[(size_t)cellList[d] * CHN + t];
        ull v2p = pk2(v, v);
        const float4 c0 = ((const float4*)coefC)[d * 2];
        const float4 c1 = ((const float4*)coefC)[d * 2 + 1];
        acc2[0] = fma2(pk2(c0.x, c0.y), v2p, acc2[0]);
        acc2[1] = fma2(pk2(c0.z, c0.w), v2p, acc2[1]);
        acc2[2] = fma2(pk2(c1.x, c1.y), v2p, acc2[2]);
        acc2[3] = fma2(pk2(c1.z, c1.w), v2p, acc2[3]);
    }
    // write interleaved by query pair: lane = kq&1
    int lane = kq & 1;
    size_t pbase = (size_t)(kq >> 1) * 8 * 512;   // floats
    #pragma unroll
    for (int p = 0; p < 4; p++) {
        float lo, hi;
        upk2(acc2[p], lo, hi);
        g_agg[pbase + (size_t)(2 * p) * 512 + t * 2 + lane]     = lo;
        g_agg[pbase + (size_t)(2 * p + 1) * 512 + t * 2 + lane] = hi;
    }
}

// ---------------- K6: per-layer tail: vp + op + LN1 + FFN + LN2 (512t, Q=16, f32x2) ----------------
__device__ __forceinline__ void ln8h(float v[8], float* redA, float* redB,
                                     float* mu, float* rs,
                                     const float* g, const float* b,
                                     int ch, int grp, int t) {
    int w = (t >> 5) & 7;
    int ln = t & 31;
    #pragma unroll
    for (int q = 0; q < 8; q++) {
        float s = v[q], s2 = v[q] * v[q];
        #pragma unroll
        for (int o = 16; o > 0; o >>= 1) {
            s  += __shfl_xor_sync(0xffffffffu, s, o);
            s2 += __shfl_xor_sync(0xffffffffu, s2, o);
        }
        if (ln == 0) { redA[(grp * 8 + q) * 8 + w] = s; redB[(grp * 8 + q) * 8 + w] = s2; }
    }
    __syncthreads();
    if (t < 16) {
        float s = 0.f, s2 = 0.f;
        #pragma unroll
        for (int k = 0; k < 8; k++) { s += redA[t * 8 + k]; s2 += redB[t * 8 + k]; }
        float m = s * (1.f / 256.f);
        mu[t] = m;
        rs[t] = rsqrtf(s2 * (1.f / 256.f) - m * m + 1e-5f);
    }
    __syncthreads();
    float gg = g[ch], bb = b[ch];
    #pragma unroll
    for (int q = 0; q < 8; q++)
        v[q] = (v[q] - mu[grp * 8 + q]) * rs[grp * 8 + q] * gg + bb;
}

__global__ __launch_bounds__(512) void k_tail(
    const float* __restrict__ vpW, const float* __restrict__ vpb,
    const float* __restrict__ opW, const float* __restrict__ opb,
    const float* __restrict__ g1, const float* __restrict__ b1,
    const float* __restrict__ W1, const float* __restrict__ fb1,
    const float* __restrict__ W2, const float* __restrict__ fb2,
    const float* __restrict__ g2, const float* __restrict__ b2) {
    __shared__ __align__(16) float bufT[256 * TS];   // transposed activations [i][q]
    __shared__ __align__(16) float qST[256 * TS];    // LN1 out (FFN input + residual)
    __shared__ float redA[16 * 8], redB[16 * 8];
    __shared__ float mu[16], rs[16];
    int t = threadIdx.x;
    int ch = t & 255;
    int grp = t >> 8;            // 0: queries 0-7, 1: queries 8-15
    int qb = grp * 8;
    int qg0 = blockIdx.x * 16;
    int h = ch >> 5;

    float v[8];

    // ---- vp (f32x2 via pair-interleaved g_agg; zero pack cost) ----
    ull acc2[4];
    #pragma unroll
    for (int p = 0; p < 4; p++) acc2[p] = pk2(0.f, 0.f);
    {
        int qp0 = (qg0 + qb) >> 1;   // base query-pair index for this grp
        #pragma unroll 2
        for (int i2 = 0; i2 < 128; i2++) {
            float w0 = vpW[(2 * i2) * CHN + ch];
            float w1 = vpW[(2 * i2 + 1) * CHN + ch];
            ull w20 = pk2(w0, w0);
            ull w21 = pk2(w1, w1);
            #pragma unroll
            for (int p = 0; p < 4; p++) {
                const ulonglong2 a = *(const ulonglong2*)&g_agg[((size_t)(qp0 + p) * 8 + h) * 512 + i2 * 4];
                acc2[p] = fma2(a.x, w20, acc2[p]);
                acc2[p] = fma2(a.y, w21, acc2[p]);
            }
        }
        float vb = vpb[ch];
        #pragma unroll
        for (int p = 0; p < 4; p++) {
            float lo, hi;
            upk2(acc2[p], lo, hi);
            bufT[ch * TS + qb + 2 * p]     = lo + g_bw[(qg0 + qb + 2 * p) * 8 + h] * vb;
            bufT[ch * TS + qb + 2 * p + 1] = hi + g_bw[(qg0 + qb + 2 * p + 1) * 8 + h] * vb;
        }
    }
    __syncthreads();

    // ---- op: q += attn @ opW + opb (f32x2) ----
    #pragma unroll
    for (int p = 0; p < 4; p++)
        acc2[p] = pk2(g_q[(qg0 + qb + 2 * p) * CHN + ch], g_q[(qg0 + qb + 2 * p + 1) * CHN + ch]);
    #pragma unroll 4
    for (int i = 0; i < 256; i++) {
        float w = opW[i * CHN + ch];
        ull w2 = pk2(w, w);
        const float4 a0 = *(const float4*)&bufT[i * TS + qb];
        const float4 a1 = *(const float4*)&bufT[i * TS + qb + 4];
        acc2[0] = fma2(pk2(a0.x, a0.y), w2, acc2[0]);
        acc2[1] = fma2(pk2(a0.z, a0.w), w2, acc2[1]);
        acc2[2] = fma2(pk2(a1.x, a1.y), w2, acc2[2]);
        acc2[3] = fma2(pk2(a1.z, a1.w), w2, acc2[3]);
    }
    {
        float ob = opb[ch];
        #pragma unroll
        for (int p = 0; p < 4; p++) {
            upk2(acc2[p], v[2 * p], v[2 * p + 1]);
            v[2 * p] += ob; v[2 * p + 1] += ob;
        }
    }

    // ---- LN1 (internal syncs also fence bufT reuse) ----
    ln8h(v, redA, redB, mu, rs, g1, b1, ch, grp, t);
    #pragma unroll
    for (int q = 0; q < 8; q++) qST[ch * TS + qb + q] = v[q];
    __syncthreads();

    // ---- FFN: 256 -> 1024 (relu) -> 256 in 4 hidden chunks (f32x2) ----
    ull o2[4];
    #pragma unroll
    for (int p = 0; p < 4; p++) o2[p] = pk2(0.f, 0.f);
    for (int chunk = 0; chunk < 4; chunk++) {
        ull h2[4];
        #pragma unroll
        for (int p = 0; p < 4; p++) h2[p] = pk2(0.f, 0.f);
        int j = chunk * CHN + ch;
        #pragma unroll 4
        for (int i = 0; i < 256; i++) {
            float w = W1[i * 1024 + j];
            ull w2 = pk2(w, w);
            const float4 a0 = *(const float4*)&qST[i * TS + qb];
            const float4 a1 = *(const float4*)&qST[i * TS + qb + 4];
            h2[0] = fma2(pk2(a0.x, a0.y), w2, h2[0]);
            h2[1] = fma2(pk2(a0.z, a0.w), w2, h2[1]);
            h2[2] = fma2(pk2(a1.x, a1.y), w2, h2[2]);
            h2[3] = fma2(pk2(a1.z, a1.w), w2, h2[3]);
        }
        float bj = fb1[j];
        #pragma unroll
        for (int p = 0; p < 4; p++) {
            float lo, hi;
            upk2(h2[p], lo, hi);
            bufT[ch * TS + qb + 2 * p]     = fmaxf(lo + bj, 0.f);
            bufT[ch * TS + qb + 2 * p + 1] = fmaxf(hi + bj, 0.f);
        }
        __syncthreads();
        #pragma unroll 4
        for (int i = 0; i < 256; i++) {
            float w = W2[(chunk * CHN + i) * CHN + ch];
            ull w2 = pk2(w, w);
            const float4 a0 = *(const float4*)&bufT[i * TS + qb];
            const float4 a1 = *(const float4*)&bufT[i * TS + qb + 4];
            o2[0] = fma2(pk2(a0.x, a0.y), w2, o2[0]);
            o2[1] = fma2(pk2(a0.z, a0.w), w2, o2[1]);
            o2[2] = fma2(pk2(a1.x, a1.y), w2, o2[2]);
            o2[3] = fma2(pk2(a1.z, a1.w), w2, o2[3]);
        }
        __syncthreads();
    }
    {
        float fb = fb2[ch];
        #pragma unroll
        for (int p = 0; p < 4; p++) {
            float lo, hi;
            upk2(o2[p], lo, hi);
            v[2 * p]     = lo + qST[ch * TS + qb + 2 * p] + fb;
            v[2 * p + 1] = hi + qST[ch * TS + qb + 2 * p + 1] + fb;
        }
    }

    // ---- LN2 ----
    ln8h(v, redA, redB, mu, rs, g2, b2, ch, grp, t);
    #pragma unroll
    for (int q = 0; q < 8; q++) g_q[(qg0 + qb + q) * CHN + ch] = v[q];
}

// ---------------- K7/K8: zero-fill output, scatter queries ----------------
__global__ void k_zero(float4* __restrict__ out) {
    out[(size_t)blockIdx.x * 256 + threadIdx.x] = make_float4(0.f, 0.f, 0.f, 0.f);
}

__global__ void k_scatter(float* __restrict__ out) {
    int k = blockIdx.x, t = threadIdx.x;
    int b = k >> 10;
    int ind = g_ind[k];
    out[(b * CHN + t) * HWSZ + ind] = g_q[k * CHN + t];
}

// ---------------- launch (fork-join: transpose+zero overlap the query chain) ----------------
extern "C" void kernel_launch(void* const* d_in, const int* in_sizes, int n_in,
                              void* d_out, int out_size) {
    const float* x    = (const float*)d_in[0];
    const float* preds= (const float*)d_in[1];
    const float* hm   = (const float*)d_in[2];
    const float* mW1  = (const float*)d_in[3];
    const float* mb1  = (const float*)d_in[4];
    const float* mW2  = (const float*)d_in[5];
    const float* mb2  = (const float*)d_in[6];
    const float* tp   = (const float*)d_in[7];
    const float* rowe = (const float*)d_in[8];
    const float* cole = (const float*)d_in[9];
    const float* soW  = (const float*)d_in[10];
    const float* sob  = (const float*)d_in[11];
    const float* awW  = (const float*)d_in[12];
    const float* awb  = (const float*)d_in[13];
    const float* vpW  = (const float*)d_in[14];
    const float* vpb  = (const float*)d_in[15];
    const float* opW  = (const float*)d_in[16];
    const float* opb  = (const float*)d_in[17];
    const float* l1g  = (const float*)d_in[18];
    const float* l1b  = (const float*)d_in[19];
    const float* fW1  = (const float*)d_in[20];
    const float* fb1  = (const float*)d_in[21];
    const float* fW2  = (const float*)d_in[22];
    const float* fb2  = (const float*)d_in[23];
    const float* l2g  = (const float*)d_in[24];
    const float* l2b  = (const float*)d_in[25];
    float* out = (float*)d_out;

    static cudaStream_t sB = nullptr;
    static cudaEvent_t evF = nullptr, evJ = nullptr;
    if (sB == nullptr) {
        cudaStreamCreateWithFlags(&sB, cudaStreamNonBlocking);
        cudaEventCreateWithFlags(&evF, cudaEventDisableTiming);
        cudaEventCreateWithFlags(&evJ, cudaEventDisableTiming);
    }

    // fork: side stream does the bulk DRAM work
    cudaEventRecord(evF, 0);
    cudaStreamWaitEvent(sB, evF, 0);
    k_transpose<<<dim3(4, 8, 1024), dim3(32, 32), 0, sB>>>(x, tp);
    k_zero<<<8192, 256, 0, sB>>>((float4*)out);
    cudaEventRecord(evJ, sB);

    // main chain: query selection + init (independent of g_val)
    k_score<<<32, 1024>>>(hm);
    k_topk<<<2, 1024>>>();
    k_qinit<<<256, 256>>>(preds, mW1, mb1, mW2, mb2, rowe, cole);
    k_soaw<<<128, 512>>>(soW, sob, awW, awb);

    // join: gather needs g_val (transpose)
    cudaStreamWaitEvent(0, evJ, 0);

    for (int l = 0; l < 3; l++) {
        if (l > 0)
            k_soaw<<<128, 512>>>(soW + l * 65536, sob + l * 256,
                                 awW + l * 32768, awb + l * 128);
        k_gather<<<2048, 256>>>();
        k_tail<<<128, 512>>>(vpW + l * 65536, vpb + l * 256,
                             opW + l * 65536, opb + l * 256,
                             l1g + l * 256, l1b + l * 256,
                             fW1 + l * 262144, fb1 + l * 1024,
                             fW2 + l * 262144, fb2 + l * 256,
                             l2g + l * 256, l2b + l * 256);
    }
    k_scatter<<<2048, 256>>>(out);
}

// round 9
// speedup vs baseline: 1.0301x; 1.0301x over previous
#include <cuda_runtime.h>
#include <math.h>

#define HWSZ 16384
#define CHN  256
#define KQ   1024
#define NQ   2048
#define HSLOTS 256
#define TS 20   // transposed activation stride in floats (80B = 16B-aligned rows)

// ---------------- device scratch (static, allocation-free) ----------------
__device__ float    g_val[(size_t)2 * 4 * HWSZ * CHN];   // [b*4+f][y][x][c], +time_pos
__device__ unsigned g_keys[2 * HWSZ];
__device__ int      g_ind[NQ];
__device__ float    g_q[NQ * CHN];
__device__ float    g_qpos[NQ * CHN];
__device__ float    g_so[NQ * CHN];
__device__ float    g_aw[NQ * 128];
__device__ float    g_agg[(size_t)NQ * 8 * CHN];   // [q][h][ch] plain layout
__device__ float    g_bw[NQ * 8];

// ---------------- f32x2 packed helpers ----------------
typedef unsigned long long ull;
__device__ __forceinline__ ull pk2(float x, float y) {
    ull r;
    asm("mov.b64 %0, {%1, %2};" : "=l"(r) : "f"(x), "f"(y));
    return r;
}
__device__ __forceinline__ void upk2(ull v, float& x, float& y) {
    asm("mov.b64 {%0, %1}, %2;" : "=f"(x), "=f"(y) : "l"(v));
}
__device__ __forceinline__ ull fma2(ull a, ull b, ull c) {
    ull d;
    asm("fma.rn.f32x2 %0, %1, %2, %3;" : "=l"(d) : "l"(a), "l"(b), "l"(c));
    return d;
}

__device__ __forceinline__ float gelu_tanh(float v) {
    float c = 0.7978845608028654f * (v + 0.044715f * v * v * v);
    return 0.5f * v * (1.0f + tanhf(c));
}

// ---------------- K1: transpose x[b,f,c,y,x] -> g_val[b,f,y,x,c] (+time_pos) ----------------
__global__ void k_transpose(const float* __restrict__ x, const float* __restrict__ tp) {
    __shared__ float tile[32][33];
    int xt = blockIdx.x * 32;
    int ct = blockIdx.y * 32;
    int z  = blockIdx.z;
    int y  = z & 127;
    int bf = z >> 7;
    int f  = bf & 3;
    int tx = threadIdx.x, ty = threadIdx.y;
    tile[ty][tx] = x[((size_t)(bf * CHN + ct + ty) * 128 + y) * 128 + xt + tx];
    __syncthreads();
    g_val[((size_t)(bf * 128 + y) * 128 + xt + ty) * CHN + ct + tx] =
        tile[tx][ty] + tp[f * CHN + ct + tx];
}

// ---------------- K2a: channel-max score -> orderable keys ----------------
__global__ __launch_bounds__(1024) void k_score(const float* __restrict__ hm) {
    int i = blockIdx.x * 1024 + threadIdx.x;
    int b = i >> 14, cell = i & (HWSZ - 1);
    const float* hb = hm + (size_t)b * 10 * HWSZ + cell;
    float m = hb[0];
    #pragma unroll
    for (int c = 1; c < 10; c++) m = fmaxf(m, hb[c * HWSZ]);
    unsigned u = __float_as_uint(m);
    u = (u & 0x80000000u) ? ~u : (u | 0x80000000u);
    g_keys[i] = u;
}

// ---------------- K2b: radix top-1024 per batch ----------------
__global__ __launch_bounds__(1024) void k_topk() {
    int b = blockIdx.x, t = threadIdx.x;
    __shared__ unsigned hist[256];
    __shared__ unsigned sh[4];

    unsigned prefix = 0, r = KQ;
    for (int byte = 3; byte >= 0; byte--) {
        if (t < 256) hist[t] = 0;
        __syncthreads();
        int sh8 = byte * 8;
        unsigned pm = (byte == 3) ? 0u : (0xFFFFFFFFu << (8 * (byte + 1)));
        for (int i = t; i < HWSZ; i += 1024) {
            unsigned k = g_keys[b * HWSZ + i];
            if ((k & pm) == (prefix & pm)) atomicAdd(&hist[(k >> sh8) & 255u], 1u);
        }
        __syncthreads();
        if (t == 0) {
            unsigned cum = 0, d = 0;
            for (int dd = 255; dd >= 0; dd--) {
                if (cum + hist[dd] >= r) { d = (unsigned)dd; break; }
                cum += hist[dd];
            }
            sh[0] = d; sh[1] = r - cum;
        }
        __syncthreads();
        prefix |= sh[0] << sh8;
        r = sh[1];
        __syncthreads();
    }
    unsigned T = prefix;
    if (t == 0) { sh[2] = 0; sh[3] = 0; }
    __syncthreads();
    for (int i = t; i < HWSZ; i += 1024)
        if (g_keys[b * HWSZ + i] > T) atomicAdd(&sh[2], 1u);
    __syncthreads();
    unsigned cgt = sh[2];
    unsigned neq = KQ - cgt;
    __syncthreads();
    if (t == 0) sh[2] = 0;
    __syncthreads();
    for (int i = t; i < HWSZ; i += 1024) {
        unsigned k = g_keys[b * HWSZ + i];
        if (k > T) {
            unsigned s = atomicAdd(&sh[2], 1u);
            g_ind[b * KQ + s] = i;
        } else if (k == T) {
            unsigned e = atomicAdd(&sh[3], 1u);
            if (e < neq) g_ind[b * KQ + cgt + e] = i;
        }
    }
}

// ---------------- K3: query-init MLP + positional embed gather ----------------
__global__ __launch_bounds__(256) void k_qinit(
    const float* __restrict__ preds,
    const float* __restrict__ W1, const float* __restrict__ b1,
    const float* __restrict__ W2, const float* __restrict__ b2,
    const float* __restrict__ rowe, const float* __restrict__ cole) {
    __shared__ float q0S[8][70];
    __shared__ float hidS[8][CHN];
    __shared__ int   indS[8];
    int t = threadIdx.x;
    int qg0 = blockIdx.x * 8;
    if (t < 8) indS[t] = g_ind[qg0 + t];
    __syncthreads();
    for (int idx = t; idx < 8 * 70; idx += 256) {
        int q = idx / 70, j = idx - q * 70;
        int b = (qg0 + q) >> 10;
        q0S[q][j] = preds[(b * 70 + j) * HWSZ + indS[q]];
    }
    #pragma unroll
    for (int q = 0; q < 8; q++) {
        int ind = indS[q];
        int xx = ind & 127, yy = ind >> 7;
        float pv = (t < 128) ? cole[xx * 128 + t] : rowe[yy * 128 + (t - 128)];
        g_qpos[(qg0 + q) * CHN + t] = pv;
    }
    __syncthreads();
    float acc[8] = {0.f,0.f,0.f,0.f,0.f,0.f,0.f,0.f};
    for (int j = 0; j < 70; j++) {
        float w = W1[j * CHN + t];
        #pragma unroll
        for (int q = 0; q < 8; q++) acc[q] += q0S[q][j] * w;
    }
    float bb = b1[t];
    #pragma unroll
    for (int q = 0; q < 8; q++) hidS[q][t] = gelu_tanh(acc[q] + bb);
    __syncthreads();
    float a2[8] = {0.f,0.f,0.f,0.f,0.f,0.f,0.f,0.f};
    for (int i = 0; i < CHN; i++) {
        float w = W2[i * CHN + t];
        #pragma unroll
        for (int q = 0; q < 8; q++) a2[q] += hidS[q][i] * w;
    }
    float b2v = b2[t];
    #pragma unroll
    for (int q = 0; q < 8; q++) g_q[(qg0 + q) * CHN + t] = a2[q] + b2v;
}

// ---------------- K4: so/aw GEMM + softmax, f32x2 zero-pack loads (512t, Q=16) ----------------
__global__ __launch_bounds__(512) void k_soaw(
    const float* __restrict__ soW, const float* __restrict__ sob,
    const float* __restrict__ awW, const float* __restrict__ awb) {
    __shared__ __align__(16) float qnT[256 * TS];   // [i][q] transposed activations
    int t = threadIdx.x;
    int qg0 = blockIdx.x * 16;

    for (int idx = t; idx < 4096; idx += 512) {
        int q = idx & 15, i = idx >> 4;
        qnT[i * TS + q] = g_q[(qg0 + q) * CHN + i] + g_qpos[(qg0 + q) * CHN + i];
    }
    __syncthreads();

    if (t < 256) {
        ull acc2[8];
        #pragma unroll
        for (int p = 0; p < 8; p++) acc2[p] = pk2(0.f, 0.f);
        #pragma unroll 4
        for (int i = 0; i < 256; i++) {
            float w = soW[i * CHN + t];
            ull w2 = pk2(w, w);
            const ulonglong2 A0 = *(const ulonglong2*)&qnT[i * TS + 0];
            const ulonglong2 A1 = *(const ulonglong2*)&qnT[i * TS + 4];
            const ulonglong2 A2 = *(const ulonglong2*)&qnT[i * TS + 8];
            const ulonglong2 A3 = *(const ulonglong2*)&qnT[i * TS + 12];
            acc2[0] = fma2(A0.x, w2, acc2[0]);
            acc2[1] = fma2(A0.y, w2, acc2[1]);
            acc2[2] = fma2(A1.x, w2, acc2[2]);
            acc2[3] = fma2(A1.y, w2, acc2[3]);
            acc2[4] = fma2(A2.x, w2, acc2[4]);
            acc2[5] = fma2(A2.y, w2, acc2[5]);
            acc2[6] = fma2(A3.x, w2, acc2[6]);
            acc2[7] = fma2(A3.y, w2, acc2[7]);
        }
        float sbv = sob[t];
        #pragma unroll
        for (int p = 0; p < 8; p++) {
            float lo, hi;
            upk2(acc2[p], lo, hi);
            g_so[(qg0 + 2 * p) * CHN + t]     = lo + sbv;
            g_so[(qg0 + 2 * p + 1) * CHN + t] = hi + sbv;
        }
    } else if (t < 384) {
        int c = t - 256;
        ull acc2[8];
        #pragma unroll
        for (int p = 0; p < 8; p++) acc2[p] = pk2(0.f, 0.f);
        #pragma unroll 4
        for (int i = 0; i < 256; i++) {
            float w = awW[i * 128 + c];
            ull w2 = pk2(w, w);
            const ulonglong2 A0 = *(const ulonglong2*)&qnT[i * TS + 0];
            const ulonglong2 A1 = *(const ulonglong2*)&qnT[i * TS + 4];
            const ulonglong2 A2 = *(const ulonglong2*)&qnT[i * TS + 8];
            const ulonglong2 A3 = *(const ulonglong2*)&qnT[i * TS + 12];
            acc2[0] = fma2(A0.x, w2, acc2[0]);
            acc2[1] = fma2(A0.y, w2, acc2[1]);
            acc2[2] = fma2(A1.x, w2, acc2[2]);
            acc2[3] = fma2(A1.y, w2, acc2[3]);
            acc2[4] = fma2(A2.x, w2, acc2[4]);
            acc2[5] = fma2(A2.y, w2, acc2[5]);
            acc2[6] = fma2(A3.x, w2, acc2[6]);
            acc2[7] = fma2(A3.y, w2, acc2[7]);
        }
        float ab = awb[c];
        float av[16];
        #pragma unroll
        for (int p = 0; p < 8; p++) {
            upk2(acc2[p], av[2 * p], av[2 * p + 1]);
            av[2 * p] += ab; av[2 * p + 1] += ab;
        }
        #pragma unroll
        for (int q = 0; q < 16; q++) {
            float vv = av[q];
            float m = vv;
            #pragma unroll
            for (int o = 8; o > 0; o >>= 1)
                m = fmaxf(m, __shfl_xor_sync(0xffffffffu, m, o, 16));
            float e = expf(vv - m);
            float s = e;
            #pragma unroll
            for (int o = 8; o > 0; o >>= 1)
                s += __shfl_xor_sync(0xffffffffu, s, o, 16);
            g_aw[(qg0 + q) * 128 + c] = e / s;
        }
    }
}

// ---------------- K5: per-query dedup gather-aggregate (1 query / block) ----------------
__global__ __launch_bounds__(256) void k_gather() {
    __shared__ __align__(16) float hcoef[HSLOTS * 8];
    __shared__ __align__(16) float coefC[HSLOTS * 8];
    __shared__ int hkey[HSLOTS];
    __shared__ int cellList[HSLOTS];
    __shared__ int cntS;

    int t = threadIdx.x;
    int kq = blockIdx.x;
    int b = kq >> 10;

    hkey[t] = -1;
    ((float4*)hcoef)[t * 2]     = make_float4(0.f, 0.f, 0.f, 0.f);
    ((float4*)hcoef)[t * 2 + 1] = make_float4(0.f, 0.f, 0.f, 0.f);
    if (t == 0) cntS = 0;
    __syncthreads();

    if (t < 128) {
        int ind = g_ind[kq];
        int h = t >> 4;
        int f = (t >> 2) & 3;
        float offx = g_so[kq * CHN + 2 * t];
        float offy = g_so[kq * CHN + 2 * t + 1];
        float aw = g_aw[kq * 128 + t];
        float xs = (float)(ind & 127) + offx;
        float ys = (float)(ind >> 7) + offy;
        float xf = floorf(xs), yf = floorf(ys);
        int x0 = (int)xf, y0 = (int)yf;
        float wx1 = xs - xf, wy1 = ys - yf;
        float wx0 = 1.f - wx1, wy0 = 1.f - wy1;
        int cxs[4] = {x0, x0 + 1, x0, x0 + 1};
        int cys[4] = {y0, y0, y0 + 1, y0 + 1};
        float cw[4] = {wx0 * wy0, wx1 * wy0, wx0 * wy1, wx1 * wy1};
        int base = (b * 4 + f) * HWSZ;
        float evs = 0.f;
        #pragma unroll
        for (int c = 0; c < 4; c++) {
            bool v = (cxs[c] >= 0) & (cxs[c] < 128) & (cys[c] >= 0) & (cys[c] < 128);
            if (v) {
                int key = base + cys[c] * 128 + cxs[c];
                float cf = aw * cw[c];
                evs += cf;
                unsigned s = ((unsigned)key * 2654435761u) >> 24;
                while (true) {
                    int prev = atomicCAS(&hkey[s], -1, key);
                    if (prev == -1 || prev == key) break;
                    s = (s + 1) & (HSLOTS - 1);
                }
                atomicAdd(&hcoef[s * 8 + h], cf);
            }
        }
        #pragma unroll
        for (int o = 8; o > 0; o >>= 1)
            evs += __shfl_xor_sync(0xffffffffu, evs, o, 16);
        if ((t & 15) == 0) g_bw[kq * 8 + h] = evs;
    }
    __syncthreads();

    {
        int key = hkey[t];
        if (key >= 0) {
            int pos = atomicAdd(&cntS, 1);
            cellList[pos] = key;
            ((float4*)coefC)[pos * 2]     = ((const float4*)hcoef)[t * 2];
            ((float4*)coefC)[pos * 2 + 1] = ((const float4*)hcoef)[t * 2 + 1];
        }
    }
    __syncthreads();
    int D = cntS;

    // aggregate: thread = channel; f32x2 zero-pack coef loads, MLP=4
    ull acc2[4];
    #pragma unroll
    for (int p = 0; p < 4; p++) acc2[p] = pk2(0.f, 0.f);
    int d = 0;
    for (; d + 4 <= D; d += 4) {
        float v0 = g_val[(size_t)cellList[d + 0] * CHN + t];
        float v1 = g_val[(size_t)cellList[d + 1] * CHN + t];
        float v2 = g_val[(size_t)cellList[d + 2] * CHN + t];
        float v3 = g_val[(size_t)cellList[d + 3] * CHN + t];
        #pragma unroll
        for (int u = 0; u < 4; u++) {
            float vv = (u == 0) ? v0 : (u == 1) ? v1 : (u == 2) ? v2 : v3;
            ull v2p = pk2(vv, vv);
            const ulonglong2 C0 = *(const ulonglong2*)&coefC[(d + u) * 8];
            const ulonglong2 C1 = *(const ulonglong2*)&coefC[(d + u) * 8 + 4];
            acc2[0] = fma2(C0.x, v2p, acc2[0]);
            acc2[1] = fma2(C0.y, v2p, acc2[1]);
            acc2[2] = fma2(C1.x, v2p, acc2[2]);
            acc2[3] = fma2(C1.y, v2p, acc2[3]);
        }
    }
    for (; d < D; d++) {
        float vv = g_val[(size_t)cellList[d] * CHN + t];
        ull v2p = pk2(vv, vv);
        const ulonglong2 C0 = *(const ulonglong2*)&coefC[d * 8];
        const ulonglong2 C1 = *(const ulonglong2*)&coefC[d * 8 + 4];
        acc2[0] = fma2(C0.x, v2p, acc2[0]);
        acc2[1] = fma2(C0.y, v2p, acc2[1]);
        acc2[2] = fma2(C1.x, v2p, acc2[2]);
        acc2[3] = fma2(C1.y, v2p, acc2[3]);
    }
    #pragma unroll
    for (int p = 0; p < 4; p++) {
        float lo, hi;
        upk2(acc2[p], lo, hi);
        g_agg[((size_t)kq * 8 + 2 * p) * CHN + t]     = lo;
        g_agg[((size_t)kq * 8 + 2 * p + 1) * CHN + t] = hi;
    }
}

// ---------------- K6: per-layer tail: vp + op + LN1 + FFN + LN2 (512t, Q=16) ----------------
__device__ __forceinline__ void ln8h(float v[8], float* redA, float* redB,
                                     float* mu, float* rs,
                                     const float* g, const float* b,
                                     int ch, int grp, int t) {
    int w = (t >> 5) & 7;
    int ln = t & 31;
    #pragma unroll
    for (int q = 0; q < 8; q++) {
        float s = v[q], s2 = v[q] * v[q];
        #pragma unroll
        for (int o = 16; o > 0; o >>= 1) {
            s  += __shfl_xor_sync(0xffffffffu, s, o);
            s2 += __shfl_xor_sync(0xffffffffu, s2, o);
        }
        if (ln == 0) { redA[(grp * 8 + q) * 8 + w] = s; redB[(grp * 8 + q) * 8 + w] = s2; }
    }
    __syncthreads();
    if (t < 16) {
        float s = 0.f, s2 = 0.f;
        #pragma unroll
        for (int k = 0; k < 8; k++) { s += redA[t * 8 + k]; s2 += redB[t * 8 + k]; }
        float m = s * (1.f / 256.f);
        mu[t] = m;
        rs[t] = rsqrtf(s2 * (1.f / 256.f) - m * m + 1e-5f);
    }
    __syncthreads();
    float gg = g[ch], bb = b[ch];
    #pragma unroll
    for (int q = 0; q < 8; q++)
        v[q] = (v[q] - mu[grp * 8 + q]) * rs[grp * 8 + q] * gg + bb;
}

__global__ __launch_bounds__(512) void k_tail(
    const float* __restrict__ vpW, const float* __restrict__ vpb,
    const float* __restrict__ opW, const float* __restrict__ opb,
    const float* __restrict__ g1, const float* __restrict__ b1,
    const float* __restrict__ W1, const float* __restrict__ fb1,
    const float* __restrict__ W2, const float* __restrict__ fb2,
    const float* __restrict__ g2, const float* __restrict__ b2) {
    __shared__ __align__(16) float bufT[256 * TS];   // transposed activations [i][q]
    __shared__ __align__(16) float qST[256 * TS];    // LN1 out (FFN input + residual)
    __shared__ float redA[16 * 8], redB[16 * 8];
    __shared__ float mu[16], rs[16];
    int t = threadIdx.x;
    int ch = t & 255;
    int grp = t >> 8;            // 0: queries 0-7, 1: queries 8-15
    int qb = grp * 8;
    int qg0 = blockIdx.x * 16;
    int h = ch >> 5;

    float v[8];

    // ---- vp: f32x2 over the reduction dim (i-pairs); 8 dual-lane accumulators ----
    {
        ull a2v[8];
        #pragma unroll
        for (int q = 0; q < 8; q++) a2v[q] = pk2(0.f, 0.f);
        for (int i4 = 0; i4 < 64; i4++) {
            float w0 = vpW[(4 * i4 + 0) * CHN + ch];
            float w1 = vpW[(4 * i4 + 1) * CHN + ch];
            float w2 = vpW[(4 * i4 + 2) * CHN + ch];
            float w3 = vpW[(4 * i4 + 3) * CHN + ch];
            ull w01 = pk2(w0, w1), w23 = pk2(w2, w3);
            #pragma unroll
            for (int q = 0; q < 8; q++) {
                const ulonglong2 a = *(const ulonglong2*)&g_agg[((size_t)(qg0 + qb + q) * 8 + h) * CHN + 4 * i4];
                a2v[q] = fma2(a.x, w01, a2v[q]);
                a2v[q] = fma2(a.y, w23, a2v[q]);
            }
        }
        float vb = vpb[ch];
        #pragma unroll
        for (int q = 0; q < 8; q++) {
            float lo, hi;
            upk2(a2v[q], lo, hi);
            bufT[ch * TS + qb + q] = lo + hi + g_bw[(qg0 + qb + q) * 8 + h] * vb;
        }
    }
    __syncthreads();

    // ---- op: q += attn @ opW + opb (f32x2, zero-pack activation loads) ----
    ull acc2[4];
    #pragma unroll
    for (int p = 0; p < 4; p++)
        acc2[p] = pk2(g_q[(qg0 + qb + 2 * p) * CHN + ch], g_q[(qg0 + qb + 2 * p + 1) * CHN + ch]);
    #pragma unroll 4
    for (int i = 0; i < 256; i++) {
        float w = opW[i * CHN + ch];
        ull w2 = pk2(w, w);
        const ulonglong2 A0 = *(const ulonglong2*)&bufT[i * TS + qb];
        const ulonglong2 A1 = *(const ulonglong2*)&bufT[i * TS + qb + 4];
        acc2[0] = fma2(A0.x, w2, acc2[0]);
        acc2[1] = fma2(A0.y, w2, acc2[1]);
        acc2[2] = fma2(A1.x, w2, acc2[2]);
        acc2[3] = fma2(A1.y, w2, acc2[3]);
    }
    {
        float ob = opb[ch];
        #pragma unroll
        for (int p = 0; p < 4; p++) {
            upk2(acc2[p], v[2 * p], v[2 * p + 1]);
            v[2 * p] += ob; v[2 * p + 1] += ob;
        }
    }

    // ---- LN1 (internal syncs also fence bufT reuse) ----
    ln8h(v, redA, redB, mu, rs, g1, b1, ch, grp, t);
    #pragma unroll
    for (int q = 0; q < 8; q++) qST[ch * TS + qb + q] = v[q];
    __syncthreads();

    // ---- FFN: 256 -> 1024 (relu) -> 256 in 4 hidden chunks (f32x2 zero-pack) ----
    ull o2[4];
    #pragma unroll
    for (int p = 0; p < 4; p++) o2[p] = pk2(0.f, 0.f);
    for (int chunk = 0; chunk < 4; chunk++) {
        ull h2[4];
        #pragma unroll
        for (int p = 0; p < 4; p++) h2[p] = pk2(0.f, 0.f);
        int j = chunk * CHN + ch;
        #pragma unroll 4
        for (int i = 0; i < 256; i++) {
            float w = W1[i * 1024 + j];
            ull w2 = pk2(w, w);
            const ulonglong2 A0 = *(const ulonglong2*)&qST[i * TS + qb];
            const ulonglong2 A1 = *(const ulonglong2*)&qST[i * TS + qb + 4];
            h2[0] = fma2(A0.x, w2, h2[0]);
            h2[1] = fma2(A0.y, w2, h2[1]);
            h2[2] = fma2(A1.x, w2, h2[2]);
            h2[3] = fma2(A1.y, w2, h2[3]);
        }
        float bj = fb1[j];
        #pragma unroll
        for (int p = 0; p < 4; p++) {
            float lo, hi;
            upk2(h2[p], lo, hi);
            bufT[ch * TS + qb + 2 * p]     = fmaxf(lo + bj, 0.f);
            bufT[ch * TS + qb + 2 * p + 1] = fmaxf(hi + bj, 0.f);
        }
        __syncthreads();
        #pragma unroll 4
        for (int i = 0; i < 256; i++) {
            float w = W2[(chunk * CHN + i) * CHN + ch];
            ull w2 = pk2(w, w);
            const ulonglong2 A0 = *(const ulonglong2*)&bufT[i * TS + qb];
            const ulonglong2 A1 = *(const ulonglong2*)&bufT[i * TS + qb + 4];
            o2[0] = fma2(A0.x, w2, o2[0]);
            o2[1] = fma2(A0.y, w2, o2[1]);
            o2[2] = fma2(A1.x, w2, o2[2]);
            o2[3] = fma2(A1.y, w2, o2[3]);
        }
        __syncthreads();
    }
    {
        float fb = fb2[ch];
        #pragma unroll
        for (int p = 0; p < 4; p++) {
            float lo, hi;
            upk2(o2[p], lo, hi);
            v[2 * p]     = lo + qST[ch * TS + qb + 2 * p] + fb;
            v[2 * p + 1] = hi + qST[ch * TS + qb + 2 * p + 1] + fb;
        }
    }

    // ---- LN2 ----
    ln8h(v, redA, redB, mu, rs, g2, b2, ch, grp, t);
    #pragma unroll
    for (int q = 0; q < 8; q++) g_q[(qg0 + qb + q) * CHN + ch] = v[q];
}

// ---------------- K7/K8: zero-fill output, scatter queries ----------------
__global__ void k_zero(float4* __restrict__ out) {
    out[(size_t)blockIdx.x * 256 + threadIdx.x] = make_float4(0.f, 0.f, 0.f, 0.f);
}

__global__ void k_scatter(float* __restrict__ out) {
    int k = blockIdx.x, t = threadIdx.x;
    int b = k >> 10;
    int ind = g_ind[k];
    out[(b * CHN + t) * HWSZ + ind] = g_q[k * CHN + t];
}

// ---------------- launch (fork-join: transpose+zero overlap the query chain) ----------------
extern "C" void kernel_launch(void* const* d_in, const int* in_sizes, int n_in,
                              void* d_out, int out_size) {
    const float* x    = (const float*)d_in[0];
    const float* preds= (const float*)d_in[1];
    const float* hm   = (const float*)d_in[2];
    const float* mW1  = (const float*)d_in[3];
    const float* mb1  = (const float*)d_in[4];
    const float* mW2  = (const float*)d_in[5];
    const float* mb2  = (const float*)d_in[6];
    const float* tp   = (const float*)d_in[7];
    const float* rowe = (const float*)d_in[8];
    const float* cole = (const float*)d_in[9];
    const float* soW  = (const float*)d_in[10];
    const float* sob  = (const float*)d_in[11];
    const float* awW  = (const float*)d_in[12];
    const float* awb  = (const float*)d_in[13];
    const float* vpW  = (const float*)d_in[14];
    const float* vpb  = (const float*)d_in[15];
    const float* opW  = (const float*)d_in[16];
    const float* opb  = (const float*)d_in[17];
    const float* l1g  = (const float*)d_in[18];
    const float* l1b  = (const float*)d_in[19];
    const float* fW1  = (const float*)d_in[20];
    const float* fb1  = (const float*)d_in[21];
    const float* fW2  = (const float*)d_in[22];
    const float* fb2  = (const float*)d_in[23];
    const float* l2g  = (const float*)d_in[24];
    const float* l2b  = (const float*)d_in[25];
    float* out = (float*)d_out;

    static cudaStream_t sB = nullptr;
    static cudaEvent_t evF = nullptr, evJ = nullptr;
    if (sB == nullptr) {
        cudaStreamCreateWithFlags(&sB, cudaStreamNonBlocking);
        cudaEventCreateWithFlags(&evF, cudaEventDisableTiming);
        cudaEventCreateWithFlags(&evJ, cudaEventDisableTiming);
    }

    // fork: side stream does the bulk DRAM work
    cudaEventRecord(evF, 0);
    cudaStreamWaitEvent(sB, evF, 0);
    k_transpose<<<dim3(4, 8, 1024), dim3(32, 32), 0, sB>>>(x, tp);
    k_zero<<<8192, 256, 0, sB>>>((float4*)out);
    cudaEventRecord(evJ, sB);

    // main chain: query selection + init (independent of g_val)
    k_score<<<32, 1024>>>(hm);
    k_topk<<<2, 1024>>>();
    k_qinit<<<256, 256>>>(preds, mW1, mb1, mW2, mb2, rowe, cole);
    k_soaw<<<128, 512>>>(soW, sob, awW, awb);

    // join: gather needs g_val (transpose)
    cudaStreamWaitEvent(0, evJ, 0);

    for (int l = 0; l < 3; l++) {
        if (l > 0)
            k_soaw<<<128, 512>>>(soW + l * 65536, sob + l * 256,
                                 awW + l * 32768, awb + l * 128);
        k_gather<<<2048, 256>>>();
        k_tail<<<128, 512>>>(vpW + l * 65536, vpb + l * 256,
                             opW + l * 65536, opb + l * 256,
                             l1g + l * 256, l1b + l * 256,
                             fW1 + l * 262144, fb1 + l * 1024,
                             fW2 + l * 262144, fb2 + l * 256,
                             l2g + l * 256, l2b + l * 256);
    }
    k_scatter<<<2048, 256>>>(out);
}

// round 10
// speedup vs baseline: 1.0736x; 1.0423x over previous
#include <cuda_runtime.h>
#include <math.h>

#define HWSZ 16384
#define CHN  256
#define KQ   1024
#define NQ   2048
#define HSLOTS 256
#define TS  20   // soaw transposed stride (16 q + 4 pad), 80B rows
#define TSB 12   // tail transposed stride (8 q + 4 pad), 48B rows

// ---------------- device scratch (static, allocation-free) ----------------
__device__ float    g_val[(size_t)2 * 4 * HWSZ * CHN];   // [b*4+f][y][x][c], +time_pos
__device__ unsigned g_keys[2 * HWSZ];
__device__ int      g_ind[NQ];
__device__ float    g_q[NQ * CHN];
__device__ float    g_qpos[NQ * CHN];
__device__ float    g_so[NQ * CHN];
__device__ float    g_aw[NQ * 128];
__device__ float    g_agg[(size_t)NQ * 8 * CHN];   // [q][h][ch]
__device__ float    g_bw[NQ * 8];

// ---------------- f32x2 packed helpers ----------------
typedef unsigned long long ull;
__device__ __forceinline__ ull pk2(float x, float y) {
    ull r;
    asm("mov.b64 %0, {%1, %2};" : "=l"(r) : "f"(x), "f"(y));
    return r;
}
__device__ __forceinline__ void upk2(ull v, float& x, float& y) {
    asm("mov.b64 {%0, %1}, %2;" : "=f"(x), "=f"(y) : "l"(v));
}
__device__ __forceinline__ ull fma2(ull a, ull b, ull c) {
    ull d;
    asm("fma.rn.f32x2 %0, %1, %2, %3;" : "=l"(d) : "l"(a), "l"(b), "l"(c));
    return d;
}

__device__ __forceinline__ float gelu_tanh(float v) {
    float c = 0.7978845608028654f * (v + 0.044715f * v * v * v);
    return 0.5f * v * (1.0f + tanhf(c));
}

// ---------------- K1: transpose x[b,f,c,y,x] -> g_val[b,f,y,x,c] (+time_pos) ----------------
__global__ void k_transpose(const float* __restrict__ x, const float* __restrict__ tp) {
    __shared__ float tile[32][33];
    int xt = blockIdx.x * 32;
    int ct = blockIdx.y * 32;
    int z  = blockIdx.z;
    int y  = z & 127;
    int bf = z >> 7;
    int f  = bf & 3;
    int tx = threadIdx.x, ty = threadIdx.y;
    tile[ty][tx] = x[((size_t)(bf * CHN + ct + ty) * 128 + y) * 128 + xt + tx];
    __syncthreads();
    g_val[((size_t)(bf * 128 + y) * 128 + xt + ty) * CHN + ct + tx] =
        tile[tx][ty] + tp[f * CHN + ct + tx];
}

// ---------------- K2a: channel-max score -> orderable keys ----------------
__global__ __launch_bounds__(1024) void k_score(const float* __restrict__ hm) {
    int i = blockIdx.x * 1024 + threadIdx.x;
    int b = i >> 14, cell = i & (HWSZ - 1);
    const float* hb = hm + (size_t)b * 10 * HWSZ + cell;
    float m = hb[0];
    #pragma unroll
    for (int c = 1; c < 10; c++) m = fmaxf(m, hb[c * HWSZ]);
    unsigned u = __float_as_uint(m);
    u = (u & 0x80000000u) ? ~u : (u | 0x80000000u);
    g_keys[i] = u;
}

// ---------------- K2b: radix top-1024 per batch ----------------
__global__ __launch_bounds__(1024) void k_topk() {
    int b = blockIdx.x, t = threadIdx.x;
    __shared__ unsigned hist[256];
    __shared__ unsigned sh[4];

    unsigned prefix = 0, r = KQ;
    for (int byte = 3; byte >= 0; byte--) {
        if (t < 256) hist[t] = 0;
        __syncthreads();
        int sh8 = byte * 8;
        unsigned pm = (byte == 3) ? 0u : (0xFFFFFFFFu << (8 * (byte + 1)));
        for (int i = t; i < HWSZ; i += 1024) {
            unsigned k = g_keys[b * HWSZ + i];
            if ((k & pm) == (prefix & pm)) atomicAdd(&hist[(k >> sh8) & 255u], 1u);
        }
        __syncthreads();
        if (t == 0) {
            unsigned cum = 0, d = 0;
            for (int dd = 255; dd >= 0; dd--) {
                if (cum + hist[dd] >= r) { d = (unsigned)dd; break; }
                cum += hist[dd];
            }
            sh[0] = d; sh[1] = r - cum;
        }
        __syncthreads();
        prefix |= sh[0] << sh8;
        r = sh[1];
        __syncthreads();
    }
    unsigned T = prefix;
    if (t == 0) { sh[2] = 0; sh[3] = 0; }
    __syncthreads();
    for (int i = t; i < HWSZ; i += 1024)
        if (g_keys[b * HWSZ + i] > T) atomicAdd(&sh[2], 1u);
    __syncthreads();
    unsigned cgt = sh[2];
    unsigned neq = KQ - cgt;
    __syncthreads();
    if (t == 0) sh[2] = 0;
    __syncthreads();
    for (int i = t; i < HWSZ; i += 1024) {
        unsigned k = g_keys[b * HWSZ + i];
        if (k > T) {
            unsigned s = atomicAdd(&sh[2], 1u);
            g_ind[b * KQ + s] = i;
        } else if (k == T) {
            unsigned e = atomicAdd(&sh[3], 1u);
            if (e < neq) g_ind[b * KQ + cgt + e] = i;
        }
    }
}

// ---------------- K3: query-init MLP + positional embed gather ----------------
__global__ __launch_bounds__(256) void k_qinit(
    const float* __restrict__ preds,
    const float* __restrict__ W1, const float* __restrict__ b1,
    const float* __restrict__ W2, const float* __restrict__ b2,
    const float* __restrict__ rowe, const float* __restrict__ cole) {
    __shared__ float q0S[8][70];
    __shared__ float hidS[8][CHN];
    __shared__ int   indS[8];
    int t = threadIdx.x;
    int qg0 = blockIdx.x * 8;
    if (t < 8) indS[t] = g_ind[qg0 + t];
    __syncthreads();
    for (int idx = t; idx < 8 * 70; idx += 256) {
        int q = idx / 70, j = idx - q * 70;
        int b = (qg0 + q) >> 10;
        q0S[q][j] = preds[(b * 70 + j) * HWSZ + indS[q]];
    }
    #pragma unroll
    for (int q = 0; q < 8; q++) {
        int ind = indS[q];
        int xx = ind & 127, yy = ind >> 7;
        float pv = (t < 128) ? cole[xx * 128 + t] : rowe[yy * 128 + (t - 128)];
        g_qpos[(qg0 + q) * CHN + t] = pv;
    }
    __syncthreads();
    float acc[8] = {0.f,0.f,0.f,0.f,0.f,0.f,0.f,0.f};
    for (int j = 0; j < 70; j++) {
        float w = W1[j * CHN + t];
        #pragma unroll
        for (int q = 0; q < 8; q++) acc[q] += q0S[q][j] * w;
    }
    float bb = b1[t];
    #pragma unroll
    for (int q = 0; q < 8; q++) hidS[q][t] = gelu_tanh(acc[q] + bb);
    __syncthreads();
    float a2[8] = {0.f,0.f,0.f,0.f,0.f,0.f,0.f,0.f};
    for (int i = 0; i < CHN; i++) {
        float w = W2[i * CHN + t];
        #pragma unroll
        for (int q = 0; q < 8; q++) a2[q] += hidS[q][i] * w;
    }
    float b2v = b2[t];
    #pragma unroll
    for (int q = 0; q < 8; q++) g_q[(qg0 + q) * CHN + t] = a2[q] + b2v;
}

// ---------------- K4: so/aw GEMM + softmax, f32x2 zero-pack loads (512t, Q=16) ----------------
__global__ __launch_bounds__(512) void k_soaw(
    const float* __restrict__ soW, const float* __restrict__ sob,
    const float* __restrict__ awW, const float* __restrict__ awb) {
    __shared__ __align__(16) float qnT[256 * TS];   // [i][q] transposed activations
    int t = threadIdx.x;
    int qg0 = blockIdx.x * 16;

    for (int idx = t; idx < 4096; idx += 512) {
        int q = idx & 15, i = idx >> 4;
        qnT[i * TS + q] = g_q[(qg0 + q) * CHN + i] + g_qpos[(qg0 + q) * CHN + i];
    }
    __syncthreads();

    if (t < 256) {
        ull acc2[8];
        #pragma unroll
        for (int p = 0; p < 8; p++) acc2[p] = pk2(0.f, 0.f);
        #pragma unroll 4
        for (int i = 0; i < 256; i++) {
            float w = soW[i * CHN + t];
            ull w2 = pk2(w, w);
            const ulonglong2 A0 = *(const ulonglong2*)&qnT[i * TS + 0];
            const ulonglong2 A1 = *(const ulonglong2*)&qnT[i * TS + 4];
            const ulonglong2 A2 = *(const ulonglong2*)&qnT[i * TS + 8];
            const ulonglong2 A3 = *(const ulonglong2*)&qnT[i * TS + 12];
            acc2[0] = fma2(A0.x, w2, acc2[0]);
            acc2[1] = fma2(A0.y, w2, acc2[1]);
            acc2[2] = fma2(A1.x, w2, acc2[2]);
            acc2[3] = fma2(A1.y, w2, acc2[3]);
            acc2[4] = fma2(A2.x, w2, acc2[4]);
            acc2[5] = fma2(A2.y, w2, acc2[5]);
            acc2[6] = fma2(A3.x, w2, acc2[6]);
            acc2[7] = fma2(A3.y, w2, acc2[7]);
        }
        float sbv = sob[t];
        #pragma unroll
        for (int p = 0; p < 8; p++) {
            float lo, hi;
            upk2(acc2[p], lo, hi);
            g_so[(qg0 + 2 * p) * CHN + t]     = lo + sbv;
            g_so[(qg0 + 2 * p + 1) * CHN + t] = hi + sbv;
        }
    } else if (t < 384) {
        int c = t - 256;
        ull acc2[8];
        #pragma unroll
        for (int p = 0; p < 8; p++) acc2[p] = pk2(0.f, 0.f);
        #pragma unroll 4
        for (int i = 0; i < 256; i++) {
            float w = awW[i * 128 + c];
            ull w2 = pk2(w, w);
            const ulonglong2 A0 = *(const ulonglong2*)&qnT[i * TS + 0];
            const ulonglong2 A1 = *(const ulonglong2*)&qnT[i * TS + 4];
            const ulonglong2 A2 = *(const ulonglong2*)&qnT[i * TS + 8];
            const ulonglong2 A3 = *(const ulonglong2*)&qnT[i * TS + 12];
            acc2[0] = fma2(A0.x, w2, acc2[0]);
            acc2[1] = fma2(A0.y, w2, acc2[1]);
            acc2[2] = fma2(A1.x, w2, acc2[2]);
            acc2[3] = fma2(A1.y, w2, acc2[3]);
            acc2[4] = fma2(A2.x, w2, acc2[4]);
            acc2[5] = fma2(A2.y, w2, acc2[5]);
            acc2[6] = fma2(A3.x, w2, acc2[6]);
            acc2[7] = fma2(A3.y, w2, acc2[7]);
        }
        float ab = awb[c];
        float av[16];
        #pragma unroll
        for (int p = 0; p < 8; p++) {
            upk2(acc2[p], av[2 * p], av[2 * p + 1]);
            av[2 * p] += ab; av[2 * p + 1] += ab;
        }
        #pragma unroll
        for (int q = 0; q < 16; q++) {
            float vv = av[q];
            float m = vv;
            #pragma unroll
            for (int o = 8; o > 0; o >>= 1)
                m = fmaxf(m, __shfl_xor_sync(0xffffffffu, m, o, 16));
            float e = expf(vv - m);
            float s = e;
            #pragma unroll
            for (int o = 8; o > 0; o >>= 1)
                s += __shfl_xor_sync(0xffffffffu, s, o, 16);
            g_aw[(qg0 + q) * 128 + c] = e / s;
        }
    }
}

// ---------------- K5: per-query dedup gather-aggregate (1 query / block) ----------------
__global__ __launch_bounds__(256) void k_gather() {
    __shared__ __align__(16) float hcoef[HSLOTS * 8];
    __shared__ __align__(16) float coefC[HSLOTS * 8];
    __shared__ int hkey[HSLOTS];
    __shared__ int cellList[HSLOTS];
    __shared__ int cntS;

    int t = threadIdx.x;
    int kq = blockIdx.x;
    int b = kq >> 10;

    hkey[t] = -1;
    ((float4*)hcoef)[t * 2]     = make_float4(0.f, 0.f, 0.f, 0.f);
    ((float4*)hcoef)[t * 2 + 1] = make_float4(0.f, 0.f, 0.f, 0.f);
    if (t == 0) cntS = 0;
    __syncthreads();

    if (t < 128) {
        int ind = g_ind[kq];
        int h = t >> 4;
        int f = (t >> 2) & 3;
        float offx = g_so[kq * CHN + 2 * t];
        float offy = g_so[kq * CHN + 2 * t + 1];
        float aw = g_aw[kq * 128 + t];
        float xs = (float)(ind & 127) + offx;
        float ys = (float)(ind >> 7) + offy;
        float xf = floorf(xs), yf = floorf(ys);
        int x0 = (int)xf, y0 = (int)yf;
        float wx1 = xs - xf, wy1 = ys - yf;
        float wx0 = 1.f - wx1, wy0 = 1.f - wy1;
        int cxs[4] = {x0, x0 + 1, x0, x0 + 1};
        int cys[4] = {y0, y0, y0 + 1, y0 + 1};
        float cw[4] = {wx0 * wy0, wx1 * wy0, wx0 * wy1, wx1 * wy1};
        int base = (b * 4 + f) * HWSZ;
        float evs = 0.f;
        #pragma unroll
        for (int c = 0; c < 4; c++) {
            bool v = (cxs[c] >= 0) & (cxs[c] < 128) & (cys[c] >= 0) & (cys[c] < 128);
            if (v) {
                int key = base + cys[c] * 128 + cxs[c];
                float cf = aw * cw[c];
                evs += cf;
                unsigned s = ((unsigned)key * 2654435761u) >> 24;
                while (true) {
                    int prev = atomicCAS(&hkey[s], -1, key);
                    if (prev == -1 || prev == key) break;
                    s = (s + 1) & (HSLOTS - 1);
                }
                atomicAdd(&hcoef[s * 8 + h], cf);
            }
        }
        #pragma unroll
        for (int o = 8; o > 0; o >>= 1)
            evs += __shfl_xor_sync(0xffffffffu, evs, o, 16);
        if ((t & 15) == 0) g_bw[kq * 8 + h] = evs;
    }
    __syncthreads();

    {
        int key = hkey[t];
        if (key >= 0) {
            int pos = atomicAdd(&cntS, 1);
            cellList[pos] = key;
            ((float4*)coefC)[pos * 2]     = ((const float4*)hcoef)[t * 2];
            ((float4*)coefC)[pos * 2 + 1] = ((const float4*)hcoef)[t * 2 + 1];
        }
    }
    __syncthreads();
    int D = cntS;

    // aggregate: thread = channel; f32x2 zero-pack coef loads, MLP=4
    ull acc2[4];
    #pragma unroll
    for (int p = 0; p < 4; p++) acc2[p] = pk2(0.f, 0.f);
    int d = 0;
    for (; d + 4 <= D; d += 4) {
        float v0 = g_val[(size_t)cellList[d + 0] * CHN + t];
        float v1 = g_val[(size_t)cellList[d + 1] * CHN + t];
        float v2 = g_val[(size_t)cellList[d + 2] * CHN + t];
        float v3 = g_val[(size_t)cellList[d + 3] * CHN + t];
        #pragma unroll
        for (int u = 0; u < 4; u++) {
            float vv = (u == 0) ? v0 : (u == 1) ? v1 : (u == 2) ? v2 : v3;
            ull v2p = pk2(vv, vv);
            const ulonglong2 C0 = *(const ulonglong2*)&coefC[(d + u) * 8];
            const ulonglong2 C1 = *(const ulonglong2*)&coefC[(d + u) * 8 + 4];
            acc2[0] = fma2(C0.x, v2p, acc2[0]);
            acc2[1] = fma2(C0.y, v2p, acc2[1]);
            acc2[2] = fma2(C1.x, v2p, acc2[2]);
            acc2[3] = fma2(C1.y, v2p, acc2[3]);
        }
    }
    for (; d < D; d++) {
        float vv = g_val[(size_t)cellList[d] * CHN + t];
        ull v2p = pk2(vv, vv);
        const ulonglong2 C0 = *(const ulonglong2*)&coefC[d * 8];
        const ulonglong2 C1 = *(const ulonglong2*)&coefC[d * 8 + 4];
        acc2[0] = fma2(C0.x, v2p, acc2[0]);
        acc2[1] = fma2(C0.y, v2p, acc2[1]);
        acc2[2] = fma2(C1.x, v2p, acc2[2]);
        acc2[3] = fma2(C1.y, v2p, acc2[3]);
    }
    #pragma unroll
    for (int p = 0; p < 4; p++) {
        float lo, hi;
        upk2(acc2[p], lo, hi);
        g_agg[((size_t)kq * 8 + 2 * p) * CHN + t]     = lo;
        g_agg[((size_t)kq * 8 + 2 * p + 1) * CHN + t] = hi;
    }
}

// ---------------- K6: per-layer tail (512t, Q=8/block, grid 256, 2 blocks/SM) ----------------
__device__ __forceinline__ void ln4h(float v[4], float* redA, float* redB,
                                     float* mu, float* rs,
                                     const float* g, const float* b,
                                     int ch, int grp, int t) {
    int w = (t >> 5) & 7;
    int ln = t & 31;
    #pragma unroll
    for (int q = 0; q < 4; q++) {
        float s = v[q], s2 = v[q] * v[q];
        #pragma unroll
        for (int o = 16; o > 0; o >>= 1) {
            s  += __shfl_xor_sync(0xffffffffu, s, o);
            s2 += __shfl_xor_sync(0xffffffffu, s2, o);
        }
        if (ln == 0) { redA[(grp * 4 + q) * 8 + w] = s; redB[(grp * 4 + q) * 8 + w] = s2; }
    }
    __syncthreads();
    if (t < 8) {
        float s = 0.f, s2 = 0.f;
        #pragma unroll
        for (int k = 0; k < 8; k++) { s += redA[t * 8 + k]; s2 += redB[t * 8 + k]; }
        float m = s * (1.f / 256.f);
        mu[t] = m;
        rs[t] = rsqrtf(s2 * (1.f / 256.f) - m * m + 1e-5f);
    }
    __syncthreads();
    float gg = g[ch], bb = b[ch];
    #pragma unroll
    for (int q = 0; q < 4; q++)
        v[q] = (v[q] - mu[grp * 4 + q]) * rs[grp * 4 + q] * gg + bb;
}

__global__ __launch_bounds__(512) void k_tail(
    const float* __restrict__ vpW, const float* __restrict__ vpb,
    const float* __restrict__ opW, const float* __restrict__ opb,
    const float* __restrict__ g1, const float* __restrict__ b1,
    const float* __restrict__ W1, const float* __restrict__ fb1,
    const float* __restrict__ W2, const float* __restrict__ fb2,
    const float* __restrict__ g2, const float* __restrict__ b2) {
    __shared__ __align__(16) float bufT[256 * TSB];  // 12KB, [i][q] transposed
    __shared__ __align__(16) float qST[256 * TSB];   // 12KB, LN1 out
    __shared__ float redA[8 * 8], redB[8 * 8];
    __shared__ float mu[8], rs[8];
    int t = threadIdx.x;
    int ch = t & 255;
    int grp = t >> 8;            // 0: queries 0-3, 1: queries 4-7
    int qb = grp * 4;
    int qg0 = blockIdx.x * 8;
    int h = ch >> 5;

    float v[4];

    // ---- vp: f32x2 over the reduction dim; dual-lane accumulators ----
    {
        ull a2v[4];
        #pragma unroll
        for (int q = 0; q < 4; q++) a2v[q] = pk2(0.f, 0.f);
        for (int i4 = 0; i4 < 64; i4++) {
            float w0 = vpW[(4 * i4 + 0) * CHN + ch];
            float w1 = vpW[(4 * i4 + 1) * CHN + ch];
            float w2 = vpW[(4 * i4 + 2) * CHN + ch];
            float w3 = vpW[(4 * i4 + 3) * CHN + ch];
            ull w01 = pk2(w0, w1), w23 = pk2(w2, w3);
            #pragma unroll
            for (int q = 0; q < 4; q++) {
                const ulonglong2 a = *(const ulonglong2*)&g_agg[((size_t)(qg0 + qb + q) * 8 + h) * CHN + 4 * i4];
                a2v[q] = fma2(a.x, w01, a2v[q]);
                a2v[q] = fma2(a.y, w23, a2v[q]);
            }
        }
        float vb = vpb[ch];
        float4 o;
        float lo, hi;
        upk2(a2v[0], lo, hi); o.x = lo + hi + g_bw[(qg0 + qb + 0) * 8 + h] * vb;
        upk2(a2v[1], lo, hi); o.y = lo + hi + g_bw[(qg0 + qb + 1) * 8 + h] * vb;
        upk2(a2v[2], lo, hi); o.z = lo + hi + g_bw[(qg0 + qb + 2) * 8 + h] * vb;
        upk2(a2v[3], lo, hi); o.w = lo + hi + g_bw[(qg0 + qb + 3) * 8 + h] * vb;
        *(float4*)&bufT[ch * TSB + qb] = o;
    }
    __syncthreads();

    // ---- op: q += attn @ opW + opb (f32x2, zero-pack activation loads) ----
    ull acc2[2];
    acc2[0] = pk2(g_q[(qg0 + qb + 0) * CHN + ch], g_q[(qg0 + qb + 1) * CHN + ch]);
    acc2[1] = pk2(g_q[(qg0 + qb + 2) * CHN + ch], g_q[(qg0 + qb + 3) * CHN + ch]);
    #pragma unroll 4
    for (int i = 0; i < 256; i++) {
        float w = opW[i * CHN + ch];
        ull w2 = pk2(w, w);
        const ulonglong2 A0 = *(const ulonglong2*)&bufT[i * TSB + qb];
        acc2[0] = fma2(A0.x, w2, acc2[0]);
        acc2[1] = fma2(A0.y, w2, acc2[1]);
    }
    {
        float ob = opb[ch];
        upk2(acc2[0], v[0], v[1]);
        upk2(acc2[1], v[2], v[3]);
        #pragma unroll
        for (int q = 0; q < 4; q++) v[q] += ob;
    }

    // ---- LN1 (internal syncs also fence bufT reuse) ----
    ln4h(v, redA, redB, mu, rs, g1, b1, ch, grp, t);
    *(float4*)&qST[ch * TSB + qb] = make_float4(v[0], v[1], v[2], v[3]);
    __syncthreads();

    // ---- FFN: 256 -> 1024 (relu) -> 256 in 4 hidden chunks (f32x2 zero-pack) ----
    ull o2[2];
    o2[0] = pk2(0.f, 0.f); o2[1] = pk2(0.f, 0.f);
    for (int chunk = 0; chunk < 4; chunk++) {
        ull h2[2];
        h2[0] = pk2(0.f, 0.f); h2[1] = pk2(0.f, 0.f);
        int j = chunk * CHN + ch;
        #pragma unroll 4
        for (int i = 0; i < 256; i++) {
            float w = W1[i * 1024 + j];
            ull w2 = pk2(w, w);
            const ulonglong2 A0 = *(const ulonglong2*)&qST[i * TSB + qb];
            h2[0] = fma2(A0.x, w2, h2[0]);
            h2[1] = fma2(A0.y, w2, h2[1]);
        }
        float bj = fb1[j];
        {
            float a, b_, c, d_;
            upk2(h2[0], a, b_);
            upk2(h2[1], c, d_);
            *(float4*)&bufT[ch * TSB + qb] = make_float4(
                fmaxf(a + bj, 0.f), fmaxf(b_ + bj, 0.f),
                fmaxf(c + bj, 0.f), fmaxf(d_ + bj, 0.f));
        }
        __syncthreads();
        #pragma unroll 4
        for (int i = 0; i < 256; i++) {
            float w = W2[(chunk * CHN + i) * CHN + ch];
            ull w2 = pk2(w, w);
            const ulonglong2 A0 = *(const ulonglong2*)&bufT[i * TSB + qb];
            o2[0] = fma2(A0.x, w2, o2[0]);
            o2[1] = fma2(A0.y, w2, o2[1]);
        }
        __syncthreads();
    }
    {
        float fb = fb2[ch];
        upk2(o2[0], v[0], v[1]);
        upk2(o2[1], v[2], v[3]);
        #pragma unroll
        for (int q = 0; q < 4; q++) v[q] += qST[ch * TSB + qb + q] + fb;
    }

    // ---- LN2 ----
    ln4h(v, redA, redB, mu, rs, g2, b2, ch, grp, t);
    #pragma unroll
    for (int q = 0; q < 4; q++) g_q[(qg0 + qb + q) * CHN + ch] = v[q];
}

// ---------------- K7/K8: zero-fill output, scatter queries ----------------
__global__ void k_zero(float4* __restrict__ out) {
    out[(size_t)blockIdx.x * 256 + threadIdx.x] = make_float4(0.f, 0.f, 0.f, 0.f);
}

__global__ void k_scatter(float* __restrict__ out) {
    int k = blockIdx.x, t = threadIdx.x;
    int b = k >> 10;
    int ind = g_ind[k];
    out[(b * CHN + t) * HWSZ + ind] = g_q[k * CHN + t];
}

// ---------------- launch (single stream) ----------------
extern "C" void kernel_launch(void* const* d_in, const int* in_sizes, int n_in,
                              void* d_out, int out_size) {
    const float* x    = (const float*)d_in[0];
    const float* preds= (const float*)d_in[1];
    const float* hm   = (const float*)d_in[2];
    const float* mW1  = (const float*)d_in[3];
    const float* mb1  = (const float*)d_in[4];
    const float* mW2  = (const float*)d_in[5];
    const float* mb2  = (const float*)d_in[6];
    const float* tp   = (const float*)d_in[7];
    const float* rowe = (const float*)d_in[8];
    const float* cole = (const float*)d_in[9];
    const float* soW  = (const float*)d_in[10];
    const float* sob  = (const float*)d_in[11];
    const float* awW  = (const float*)d_in[12];
    const float* awb  = (const float*)d_in[13];
    const float* vpW  = (const float*)d_in[14];
    const float* vpb  = (const float*)d_in[15];
    const float* opW  = (const float*)d_in[16];
    const float* opb  = (const float*)d_in[17];
    const float* l1g  = (const float*)d_in[18];
    const float* l1b  = (const float*)d_in[19];
    const float* fW1  = (const float*)d_in[20];
    const float* fb1  = (const float*)d_in[21];
    const float* fW2  = (const float*)d_in[22];
    const float* fb2  = (const float*)d_in[23];
    const float* l2g  = (const float*)d_in[24];
    const float* l2b  = (const float*)d_in[25];
    float* out = (float*)d_out;

    k_transpose<<<dim3(4, 8, 1024), dim3(32, 32)>>>(x, tp);
    k_score<<<32, 1024>>>(hm);
    k_topk<<<2, 1024>>>();
    k_qinit<<<256, 256>>>(preds, mW1, mb1, mW2, mb2, rowe, cole);
    for (int l = 0; l < 3; l++) {
        k_soaw<<<128, 512>>>(soW + l * 65536, sob + l * 256,
                             awW + l * 32768, awb + l * 128);
        k_gather<<<2048, 256>>>();
        k_tail<<<256, 512>>>(vpW + l * 65536, vpb + l * 256,
                             opW + l * 65536, opb + l * 256,
                             l1g + l * 256, l1b + l * 256,
                             fW1 + l * 262144, fb1 + l * 1024,
                             fW2 + l * 262144, fb2 + l * 256,
                             l2g + l * 256, l2b + l * 256);
    }
    k_zero<<<8192, 256>>>((float4*)out);
    k_scatter<<<2048, 256>>>(out);
}

// round 11
// speedup vs baseline: 1.0829x; 1.0087x over previous
#include <cuda_runtime.h>
#include <math.h>

#define HWSZ 16384
#define CHN  256
#define KQ   1024
#define NQ   2048
#define HSLOTS 256
#define TSB 12   // transposed activation stride (8 q + 4 pad), 48B = 16B-aligned rows

// ---------------- device scratch (static, allocation-free) ----------------
__device__ float    g_val[(size_t)2 * 4 * HWSZ * CHN];   // [b*4+f][y][x][c], +time_pos
__device__ unsigned g_keys[2 * HWSZ];
__device__ int      g_ind[NQ];
__device__ float    g_q[NQ * CHN];
__device__ float    g_qpos[NQ * CHN];
__device__ float    g_so[NQ * CHN];
__device__ float    g_aw[NQ * 128];
__device__ float    g_agg[(size_t)NQ * 8 * CHN];   // [q][h][ch]
__device__ float    g_bw[NQ * 8];

// ---------------- f32x2 packed helpers ----------------
typedef unsigned long long ull;
__device__ __forceinline__ ull pk2(float x, float y) {
    ull r;
    asm("mov.b64 %0, {%1, %2};" : "=l"(r) : "f"(x), "f"(y));
    return r;
}
__device__ __forceinline__ void upk2(ull v, float& x, float& y) {
    asm("mov.b64 {%0, %1}, %2;" : "=f"(x), "=f"(y) : "l"(v));
}
__device__ __forceinline__ ull fma2(ull a, ull b, ull c) {
    ull d;
    asm("fma.rn.f32x2 %0, %1, %2, %3;" : "=l"(d) : "l"(a), "l"(b), "l"(c));
    return d;
}

__device__ __forceinline__ float gelu_tanh(float v) {
    float c = 0.7978845608028654f * (v + 0.044715f * v * v * v);
    return 0.5f * v * (1.0f + tanhf(c));
}

// ---------------- K1: transpose x[b,f,c,y,x] -> g_val[b,f,y,x,c] (+time_pos) ----------------
__global__ void k_transpose(const float* __restrict__ x, const float* __restrict__ tp) {
    __shared__ float tile[32][33];
    int xt = blockIdx.x * 32;
    int ct = blockIdx.y * 32;
    int z  = blockIdx.z;
    int y  = z & 127;
    int bf = z >> 7;
    int f  = bf & 3;
    int tx = threadIdx.x, ty = threadIdx.y;
    tile[ty][tx] = x[((size_t)(bf * CHN + ct + ty) * 128 + y) * 128 + xt + tx];
    __syncthreads();
    g_val[((size_t)(bf * 128 + y) * 128 + xt + ty) * CHN + ct + tx] =
        tile[tx][ty] + tp[f * CHN + ct + tx];
}

// ---------------- K2a: channel-max score -> orderable keys ----------------
__global__ __launch_bounds__(1024) void k_score(const float* __restrict__ hm) {
    int i = blockIdx.x * 1024 + threadIdx.x;
    int b = i >> 14, cell = i & (HWSZ - 1);
    const float* hb = hm + (size_t)b * 10 * HWSZ + cell;
    float m = hb[0];
    #pragma unroll
    for (int c = 1; c < 10; c++) m = fmaxf(m, hb[c * HWSZ]);
    unsigned u = __float_as_uint(m);
    u = (u & 0x80000000u) ? ~u : (u | 0x80000000u);
    g_keys[i] = u;
}

// ---------------- K2b: radix top-1024 per batch (parallel suffix-scan select) ----------------
__global__ __launch_bounds__(1024) void k_topk() {
    int b = blockIdx.x, t = threadIdx.x;
    __shared__ unsigned hist[256];
    __shared__ unsigned suf[256];
    __shared__ unsigned sh[4];

    unsigned prefix = 0, r = KQ;
    for (int byte = 3; byte >= 0; byte--) {
        if (t < 256) hist[t] = 0;
        __syncthreads();
        int sh8 = byte * 8;
        unsigned pm = (byte == 3) ? 0u : (0xFFFFFFFFu << (8 * (byte + 1)));
        for (int i = t; i < HWSZ; i += 1024) {
            unsigned k = g_keys[b * HWSZ + i];
            if ((k & pm) == (prefix & pm)) atomicAdd(&hist[(k >> sh8) & 255u], 1u);
        }
        __syncthreads();
        if (t < 256) suf[t] = hist[t];
        __syncthreads();
        // inclusive suffix scan: suf[t] = sum_{dd >= t} hist[dd]
        #pragma unroll
        for (int off = 1; off < 256; off <<= 1) {
            unsigned add = 0;
            if (t < 256 && t + off < 256) add = suf[t + off];
            __syncthreads();
            if (t < 256) suf[t] += add;
            __syncthreads();
        }
        if (t < 256) {
            unsigned nxt = (t == 255) ? 0u : suf[t + 1];
            if (suf[t] >= r && nxt < r) { sh[0] = (unsigned)t; sh[1] = r - nxt; }
        }
        __syncthreads();
        prefix |= sh[0] << sh8;
        r = sh[1];
        __syncthreads();
    }
    unsigned T = prefix;
    if (t == 0) { sh[2] = 0; sh[3] = 0; }
    __syncthreads();
    for (int i = t; i < HWSZ; i += 1024)
        if (g_keys[b * HWSZ + i] > T) atomicAdd(&sh[2], 1u);
    __syncthreads();
    unsigned cgt = sh[2];
    unsigned neq = KQ - cgt;
    __syncthreads();
    if (t == 0) sh[2] = 0;
    __syncthreads();
    for (int i = t; i < HWSZ; i += 1024) {
        unsigned k = g_keys[b * HWSZ + i];
        if (k > T) {
            unsigned s = atomicAdd(&sh[2], 1u);
            g_ind[b * KQ + s] = i;
        } else if (k == T) {
            unsigned e = atomicAdd(&sh[3], 1u);
            if (e < neq) g_ind[b * KQ + cgt + e] = i;
        }
    }
}

// ---------------- K3: query-init MLP + positional embed gather (4 q/block, grid 512) ----------------
__global__ __launch_bounds__(256) void k_qinit(
    const float* __restrict__ preds,
    const float* __restrict__ W1, const float* __restrict__ b1,
    const float* __restrict__ W2, const float* __restrict__ b2,
    const float* __restrict__ rowe, const float* __restrict__ cole) {
    __shared__ float q0S[4][70];
    __shared__ float hidS[4][CHN];
    __shared__ int   indS[4];
    int t = threadIdx.x;
    int qg0 = blockIdx.x * 4;
    if (t < 4) indS[t] = g_ind[qg0 + t];
    __syncthreads();
    for (int idx = t; idx < 4 * 70; idx += 256) {
        int q = idx / 70, j = idx - q * 70;
        int b = (qg0 + q) >> 10;
        q0S[q][j] = preds[(b * 70 + j) * HWSZ + indS[q]];
    }
    #pragma unroll
    for (int q = 0; q < 4; q++) {
        int ind = indS[q];
        int xx = ind & 127, yy = ind >> 7;
        float pv = (t < 128) ? cole[xx * 128 + t] : rowe[yy * 128 + (t - 128)];
        g_qpos[(qg0 + q) * CHN + t] = pv;
    }
    __syncthreads();
    float acc[4] = {0.f,0.f,0.f,0.f};
    for (int j = 0; j < 70; j++) {
        float w = W1[j * CHN + t];
        #pragma unroll
        for (int q = 0; q < 4; q++) acc[q] += q0S[q][j] * w;
    }
    float bb = b1[t];
    #pragma unroll
    for (int q = 0; q < 4; q++) hidS[q][t] = gelu_tanh(acc[q] + bb);
    __syncthreads();
    float a2[4] = {0.f,0.f,0.f,0.f};
    for (int i = 0; i < CHN; i++) {
        float w = W2[i * CHN + t];
        #pragma unroll
        for (int q = 0; q < 4; q++) a2[q] += hidS[q][i] * w;
    }
    float b2v = b2[t];
    #pragma unroll
    for (int q = 0; q < 4; q++) g_q[(qg0 + q) * CHN + t] = a2[q] + b2v;
}

// ---------------- K4: so/aw GEMM + softmax (384t, Q=8, grid 256) ----------------
__global__ __launch_bounds__(384) void k_soaw(
    const float* __restrict__ soW, const float* __restrict__ sob,
    const float* __restrict__ awW, const float* __restrict__ awb) {
    __shared__ __align__(16) float qnT[256 * TSB];   // [i][q] transposed activations
    int t = threadIdx.x;
    int qg0 = blockIdx.x * 8;

    for (int idx = t; idx < 2048; idx += 384) {
        int q = idx & 7, i = idx >> 3;
        qnT[i * TSB + q] = g_q[(qg0 + q) * CHN + i] + g_qpos[(qg0 + q) * CHN + i];
    }
    __syncthreads();

    if (t < 256) {
        // so: out channel = t, 8 queries as 4 f32x2 pairs
        ull acc2[4];
        #pragma unroll
        for (int p = 0; p < 4; p++) acc2[p] = pk2(0.f, 0.f);
        #pragma unroll 4
        for (int i = 0; i < 256; i++) {
            float w = soW[i * CHN + t];
            ull w2 = pk2(w, w);
            const ulonglong2 A0 = *(const ulonglong2*)&qnT[i * TSB + 0];
            const ulonglong2 A1 = *(const ulonglong2*)&qnT[i * TSB + 4];
            acc2[0] = fma2(A0.x, w2, acc2[0]);
            acc2[1] = fma2(A0.y, w2, acc2[1]);
            acc2[2] = fma2(A1.x, w2, acc2[2]);
            acc2[3] = fma2(A1.y, w2, acc2[3]);
        }
        float sbv = sob[t];
        #pragma unroll
        for (int p = 0; p < 4; p++) {
            float lo, hi;
            upk2(acc2[p], lo, hi);
            g_so[(qg0 + 2 * p) * CHN + t]     = lo + sbv;
            g_so[(qg0 + 2 * p + 1) * CHN + t] = hi + sbv;
        }
    } else {
        // aw: out channel = t-256 (128 outs), 8 queries; then 16-wide softmax
        int c = t - 256;
        ull acc2[4];
        #pragma unroll
        for (int p = 0; p < 4; p++) acc2[p] = pk2(0.f, 0.f);
        #pragma unroll 4
        for (int i = 0; i < 256; i++) {
            float w = awW[i * 128 + c];
            ull w2 = pk2(w, w);
            const ulonglong2 A0 = *(const ulonglong2*)&qnT[i * TSB + 0];
            const ulonglong2 A1 = *(const ulonglong2*)&qnT[i * TSB + 4];
            acc2[0] = fma2(A0.x, w2, acc2[0]);
            acc2[1] = fma2(A0.y, w2, acc2[1]);
            acc2[2] = fma2(A1.x, w2, acc2[2]);
            acc2[3] = fma2(A1.y, w2, acc2[3]);
        }
        float ab = awb[c];
        float av[8];
        #pragma unroll
        for (int p = 0; p < 4; p++) {
            upk2(acc2[p], av[2 * p], av[2 * p + 1]);
            av[2 * p] += ab; av[2 * p + 1] += ab;
        }
        #pragma unroll
        for (int q = 0; q < 8; q++) {
            float vv = av[q];
            float m = vv;
            #pragma unroll
            for (int o = 8; o > 0; o >>= 1)
                m = fmaxf(m, __shfl_xor_sync(0xffffffffu, m, o, 16));
            float e = expf(vv - m);
            float s = e;
            #pragma unroll
            for (int o = 8; o > 0; o >>= 1)
                s += __shfl_xor_sync(0xffffffffu, s, o, 16);
            g_aw[(qg0 + q) * 128 + c] = e / s;
        }
    }
}

// ---------------- K5: per-query dedup gather-aggregate (1 query / block) ----------------
__global__ __launch_bounds__(256) void k_gather() {
    __shared__ __align__(16) float hcoef[HSLOTS * 8];
    __shared__ __align__(16) float coefC[HSLOTS * 8];
    __shared__ int hkey[HSLOTS];
    __shared__ int cellList[HSLOTS];
    __shared__ int cntS;

    int t = threadIdx.x;
    int kq = blockIdx.x;
    int b = kq >> 10;

    hkey[t] = -1;
    ((float4*)hcoef)[t * 2]     = make_float4(0.f, 0.f, 0.f, 0.f);
    ((float4*)hcoef)[t * 2 + 1] = make_float4(0.f, 0.f, 0.f, 0.f);
    if (t == 0) cntS = 0;
    __syncthreads();

    if (t < 128) {
        int ind = g_ind[kq];
        int h = t >> 4;
        int f = (t >> 2) & 3;
        float offx = g_so[kq * CHN + 2 * t];
        float offy = g_so[kq * CHN + 2 * t + 1];
        float aw = g_aw[kq * 128 + t];
        float xs = (float)(ind & 127) + offx;
        float ys = (float)(ind >> 7) + offy;
        float xf = floorf(xs), yf = floorf(ys);
        int x0 = (int)xf, y0 = (int)yf;
        float wx1 = xs - xf, wy1 = ys - yf;
        float wx0 = 1.f - wx1, wy0 = 1.f - wy1;
        int cxs[4] = {x0, x0 + 1, x0, x0 + 1};
        int cys[4] = {y0, y0, y0 + 1, y0 + 1};
        float cw[4] = {wx0 * wy0, wx1 * wy0, wx0 * wy1, wx1 * wy1};
        int base = (b * 4 + f) * HWSZ;
        float evs = 0.f;
        #pragma unroll
        for (int c = 0; c < 4; c++) {
            bool v = (cxs[c] >= 0) & (cxs[c] < 128) & (cys[c] >= 0) & (cys[c] < 128);
            if (v) {
                int key = base + cys[c] * 128 + cxs[c];
                float cf = aw * cw[c];
                evs += cf;
                unsigned s = ((unsigned)key * 2654435761u) >> 24;
                while (true) {
                    int prev = atomicCAS(&hkey[s], -1, key);
                    if (prev == -1 || prev == key) break;
                    s = (s + 1) & (HSLOTS - 1);
                }
                atomicAdd(&hcoef[s * 8 + h], cf);
            }
        }
        #pragma unroll
        for (int o = 8; o > 0; o >>= 1)
            evs += __shfl_xor_sync(0xffffffffu, evs, o, 16);
        if ((t & 15) == 0) g_bw[kq * 8 + h] = evs;
    }
    __syncthreads();

    {
        int key = hkey[t];
        if (key >= 0) {
            int pos = atomicAdd(&cntS, 1);
            cellList[pos] = key;
            ((float4*)coefC)[pos * 2]     = ((const float4*)hcoef)[t * 2];
            ((float4*)coefC)[pos * 2 + 1] = ((const float4*)hcoef)[t * 2 + 1];
        }
    }
    __syncthreads();
    int D = cntS;

    // aggregate: thread = channel; f32x2 zero-pack coef loads, MLP=4
    ull acc2[4];
    #pragma unroll
    for (int p = 0; p < 4; p++) acc2[p] = pk2(0.f, 0.f);
    int d = 0;
    for (; d + 4 <= D; d += 4) {
        float v0 = g_val[(size_t)cellList[d + 0] * CHN + t];
        float v1 = g_val[(size_t)cellList[d + 1] * CHN + t];
        float v2 = g_val[(size_t)cellList[d + 2] * CHN + t];
        float v3 = g_val[(size_t)cellList[d + 3] * CHN + t];
        #pragma unroll
        for (int u = 0; u < 4; u++) {
            float vv = (u == 0) ? v0 : (u == 1) ? v1 : (u == 2) ? v2 : v3;
            ull v2p = pk2(vv, vv);
            const ulonglong2 C0 = *(const ulonglong2*)&coefC[(d + u) * 8];
            const ulonglong2 C1 = *(const ulonglong2*)&coefC[(d + u) * 8 + 4];
            acc2[0] = fma2(C0.x, v2p, acc2[0]);
            acc2[1] = fma2(C0.y, v2p, acc2[1]);
            acc2[2] = fma2(C1.x, v2p, acc2[2]);
            acc2[3] = fma2(C1.y, v2p, acc2[3]);
        }
    }
    for (; d < D; d++) {
        float vv = g_val[(size_t)cellList[d] * CHN + t];
        ull v2p = pk2(vv, vv);
        const ulonglong2 C0 = *(const ulonglong2*)&coefC[d * 8];
        const ulonglong2 C1 = *(const ulonglong2*)&coefC[d * 8 + 4];
        acc2[0] = fma2(C0.x, v2p, acc2[0]);
        acc2[1] = fma2(C0.y, v2p, acc2[1]);
        acc2[2] = fma2(C1.x, v2p, acc2[2]);
        acc2[3] = fma2(C1.y, v2p, acc2[3]);
    }
    #pragma unroll
    for (int p = 0; p < 4; p++) {
        float lo, hi;
        upk2(acc2[p], lo, hi);
        g_agg[((size_t)kq * 8 + 2 * p) * CHN + t]     = lo;
        g_agg[((size_t)kq * 8 + 2 * p + 1) * CHN + t] = hi;
    }
}

// ---------------- K6: per-layer tail (512t, Q=8/block, grid 256, 2 blocks/SM) ----------------
__device__ __forceinline__ void ln4h(float v[4], float* redA, float* redB,
                                     float* mu, float* rs,
                                     const float* g, const float* b,
                                     int ch, int grp, int t) {
    int w = (t >> 5) & 7;
    int ln = t & 31;
    #pragma unroll
    for (int q = 0; q < 4; q++) {
        float s = v[q], s2 = v[q] * v[q];
        #pragma unroll
        for (int o = 16; o > 0; o >>= 1) {
            s  += __shfl_xor_sync(0xffffffffu, s, o);
            s2 += __shfl_xor_sync(0xffffffffu, s2, o);
        }
        if (ln == 0) { redA[(grp * 4 + q) * 8 + w] = s; redB[(grp * 4 + q) * 8 + w] = s2; }
    }
    __syncthreads();
    if (t < 8) {
        float s = 0.f, s2 = 0.f;
        #pragma unroll
        for (int k = 0; k < 8; k++) { s += redA[t * 8 + k]; s2 += redB[t * 8 + k]; }
        float m = s * (1.f / 256.f);
        mu[t] = m;
        rs[t] = rsqrtf(s2 * (1.f / 256.f) - m * m + 1e-5f);
    }
    __syncthreads();
    float gg = g[ch], bb = b[ch];
    #pragma unroll
    for (int q = 0; q < 4; q++)
        v[q] = (v[q] - mu[grp * 4 + q]) * rs[grp * 4 + q] * gg + bb;
}

__global__ __launch_bounds__(512) void k_tail(
    const float* __restrict__ vpW, const float* __restrict__ vpb,
    const float* __restrict__ opW, const float* __restrict__ opb,
    const float* __restrict__ g1, const float* __restrict__ b1,
    const float* __restrict__ W1, const float* __restrict__ fb1,
    const float* __restrict__ W2, const float* __restrict__ fb2,
    const float* __restrict__ g2, const float* __restrict__ b2) {
    __shared__ __align__(16) float bufT[256 * TSB];  // 12KB, [i][q] transposed
    __shared__ __align__(16) float qST[256 * TSB];   // 12KB, LN1 out
    __shared__ float redA[8 * 8], redB[8 * 8];
    __shared__ float mu[8], rs[8];
    int t = threadIdx.x;
    int ch = t & 255;
    int grp = t >> 8;            // 0: queries 0-3, 1: queries 4-7
    int qb = grp * 4;
    int qg0 = blockIdx.x * 8;
    int h = ch >> 5;

    float v[4];

    // ---- vp: f32x2 over the reduction dim; dual-lane accumulators ----
    {
        ull a2v[4];
        #pragma unroll
        for (int q = 0; q < 4; q++) a2v[q] = pk2(0.f, 0.f);
        for (int i4 = 0; i4 < 64; i4++) {
            float w0 = vpW[(4 * i4 + 0) * CHN + ch];
            float w1 = vpW[(4 * i4 + 1) * CHN + ch];
            float w2 = vpW[(4 * i4 + 2) * CHN + ch];
            float w3 = vpW[(4 * i4 + 3) * CHN + ch];
            ull w01 = pk2(w0, w1), w23 = pk2(w2, w3);
            #pragma unroll
            for (int q = 0; q < 4; q++) {
                const ulonglong2 a = *(const ulonglong2*)&g_agg[((size_t)(qg0 + qb + q) * 8 + h) * CHN + 4 * i4];
                a2v[q] = fma2(a.x, w01, a2v[q]);
                a2v[q] = fma2(a.y, w23, a2v[q]);
            }
        }
        float vb = vpb[ch];
        float4 o;
        float lo, hi;
        upk2(a2v[0], lo, hi); o.x = lo + hi + g_bw[(qg0 + qb + 0) * 8 + h] * vb;
        upk2(a2v[1], lo, hi); o.y = lo + hi + g_bw[(qg0 + qb + 1) * 8 + h] * vb;
        upk2(a2v[2], lo, hi); o.z = lo + hi + g_bw[(qg0 + qb + 2) * 8 + h] * vb;
        upk2(a2v[3], lo, hi); o.w = lo + hi + g_bw[(qg0 + qb + 3) * 8 + h] * vb;
        *(float4*)&bufT[ch * TSB + qb] = o;
    }
    __syncthreads();

    // ---- op: q += attn @ opW + opb (f32x2, zero-pack activation loads) ----
    ull acc2[2];
    acc2[0] = pk2(g_q[(qg0 + qb + 0) * CHN + ch], g_q[(qg0 + qb + 1) * CHN + ch]);
    acc2[1] = pk2(g_q[(qg0 + qb + 2) * CHN + ch], g_q[(qg0 + qb + 3) * CHN + ch]);
    #pragma unroll 4
    for (int i = 0; i < 256; i++) {
        float w = opW[i * CHN + ch];
        ull w2 = pk2(w, w);
        const ulonglong2 A0 = *(const ulonglong2*)&bufT[i * TSB + qb];
        acc2[0] = fma2(A0.x, w2, acc2[0]);
        acc2[1] = fma2(A0.y, w2, acc2[1]);
    }
    {
        float ob = opb[ch];
        upk2(acc2[0], v[0], v[1]);
        upk2(acc2[1], v[2], v[3]);
        #pragma unroll
        for (int q = 0; q < 4; q++) v[q] += ob;
    }

    // ---- LN1 (internal syncs also fence bufT reuse) ----
    ln4h(v, redA, redB, mu, rs, g1, b1, ch, grp, t);
    *(float4*)&qST[ch * TSB + qb] = make_float4(v[0], v[1], v[2], v[3]);
    __syncthreads();

    // ---- FFN: 256 -> 1024 (relu) -> 256 in 4 hidden chunks (f32x2 zero-pack) ----
    ull o2[2];
    o2[0] = pk2(0.f, 0.f); o2[1] = pk2(0.f, 0.f);
    for (int chunk = 0; chunk < 4; chunk++) {
        ull h2[2];
        h2[0] = pk2(0.f, 0.f); h2[1] = pk2(0.f, 0.f);
        int j = chunk * CHN + ch;
        #pragma unroll 4
        for (int i = 0; i < 256; i++) {
            float w = W1[i * 1024 + j];
            ull w2 = pk2(w, w);
            const ulonglong2 A0 = *(const ulonglong2*)&qST[i * TSB + qb];
            h2[0] = fma2(A0.x, w2, h2[0]);
            h2[1] = fma2(A0.y, w2, h2[1]);
        }
        float bj = fb1[j];
        {
            float a, b_, c, d_;
            upk2(h2[0], a, b_);
            upk2(h2[1], c, d_);
            *(float4*)&bufT[ch * TSB + qb] = make_float4(
                fmaxf(a + bj, 0.f), fmaxf(b_ + bj, 0.f),
                fmaxf(c + bj, 0.f), fmaxf(d_ + bj, 0.f));
        }
        __syncthreads();
        #pragma unroll 4
        for (int i = 0; i < 256; i++) {
            float w = W2[(chunk * CHN + i) * CHN + ch];
            ull w2 = pk2(w, w);
            const ulonglong2 A0 = *(const ulonglong2*)&bufT[i * TSB + qb];
            o2[0] = fma2(A0.x, w2, o2[0]);
            o2[1] = fma2(A0.y, w2, o2[1]);
        }
        __syncthreads();
    }
    {
        float fb = fb2[ch];
        upk2(o2[0], v[0], v[1]);
        upk2(o2[1], v[2], v[3]);
        #pragma unroll
        for (int q = 0; q < 4; q++) v[q] += qST[ch * TSB + qb + q] + fb;
    }

    // ---- LN2 ----
    ln4h(v, redA, redB, mu, rs, g2, b2, ch, grp, t);
    #pragma unroll
    for (int q = 0; q < 4; q++) g_q[(qg0 + qb + q) * CHN + ch] = v[q];
}

// ---------------- K7/K8: zero-fill output, scatter queries ----------------
__global__ void k_zero(float4* __restrict__ out) {
    out[(size_t)blockIdx.x * 256 + threadIdx.x] = make_float4(0.f, 0.f, 0.f, 0.f);
}

__global__ void k_scatter(float* __restrict__ out) {
    int k = blockIdx.x, t = threadIdx.x;
    int b = k >> 10;
    int ind = g_ind[k];
    out[(b * CHN + t) * HWSZ + ind] = g_q[k * CHN + t];
}

// ---------------- launch (single stream) ----------------
extern "C" void kernel_launch(void* const* d_in, const int* in_sizes, int n_in,
                              void* d_out, int out_size) {
    const float* x    = (const float*)d_in[0];
    const float* preds= (const float*)d_in[1];
    const float* hm   = (const float*)d_in[2];
    const float* mW1  = (const float*)d_in[3];
    const float* mb1  = (const float*)d_in[4];
    const float* mW2  = (const float*)d_in[5];
    const float* mb2  = (const float*)d_in[6];
    const float* tp   = (const float*)d_in[7];
    const float* rowe = (const float*)d_in[8];
    const float* cole = (const float*)d_in[9];
    const float* soW  = (const float*)d_in[10];
    const float* sob  = (const float*)d_in[11];
    const float* awW  = (const float*)d_in[12];
    const float* awb  = (const float*)d_in[13];
    const float* vpW  = (const float*)d_in[14];
    const float* vpb  = (const float*)d_in[15];
    const float* opW  = (const float*)d_in[16];
    const float* opb  = (const float*)d_in[17];
    const float* l1g  = (const float*)d_in[18];
    const float* l1b  = (const float*)d_in[19];
    const float* fW1  = (const float*)d_in[20];
    const float* fb1  = (const float*)d_in[21];
    const float* fW2  = (const float*)d_in[22];
    const float* fb2  = (const float*)d_in[23];
    const float* l2g  = (const float*)d_in[24];
    const float* l2b  = (const float*)d_in[25];
    float* out = (float*)d_out;

    k_transpose<<<dim3(4, 8, 1024), dim3(32, 32)>>>(x, tp);
    k_score<<<32, 1024>>>(hm);
    k_topk<<<2, 1024>>>();
    k_qinit<<<512, 256>>>(preds, mW1, mb1, mW2, mb2, rowe, cole);
    for (int l = 0; l < 3; l++) {
        k_soaw<<<256, 384>>>(soW + l * 65536, sob + l * 256,
                             awW + l * 32768, awb + l * 128);
        k_gather<<<2048, 256>>>();
        k_tail<<<256, 512>>>(vpW + l * 65536, vpb + l * 256,
                             opW + l * 65536, opb + l * 256,
                             l1g + l * 256, l1b + l * 256,
                             fW1 + l * 262144, fb1 + l * 1024,
                             fW2 + l * 262144, fb2 + l * 256,
                             l2g + l * 256, l2b + l * 256);
    }
    k_zero<<<8192, 256>>>((float4*)out);
    k_scatter<<<2048, 256>>>(out);
}

// round 12
// speedup vs baseline: 1.1596x; 1.0708x over previous
#include <cuda_runtime.h>
#include <math.h>

#define HWSZ 16384
#define CHN  256
#define KQ   1024
#define NQ   2048
#define HSLOTS 256
#define TSB 12   // transposed activation stride (8 q + 4 pad), 48B = 16B-aligned rows

// ---------------- device scratch (static, allocation-free) ----------------
__device__ float    g_val[(size_t)2 * 4 * HWSZ * CHN];   // [b*4+f][y][x][c], +time_pos
__device__ unsigned g_keys[2 * HWSZ];
__device__ int      g_ind[NQ];
__device__ float    g_q[NQ * CHN];
__device__ float    g_qpos[NQ * CHN];
__device__ float    g_so[NQ * CHN];
__device__ float    g_aw[NQ * 128];
__device__ float    g_agg[(size_t)NQ * 8 * CHN];   // [q][h][ch]
__device__ float    g_bw[NQ * 8];

// ---------------- f32x2 packed helpers ----------------
typedef unsigned long long ull;
__device__ __forceinline__ ull pk2(float x, float y) {
    ull r;
    asm("mov.b64 %0, {%1, %2};" : "=l"(r) : "f"(x), "f"(y));
    return r;
}
__device__ __forceinline__ void upk2(ull v, float& x, float& y) {
    asm("mov.b64 {%0, %1}, %2;" : "=f"(x), "=f"(y) : "l"(v));
}
__device__ __forceinline__ ull fma2(ull a, ull b, ull c) {
    ull d;
    asm("fma.rn.f32x2 %0, %1, %2, %3;" : "=l"(d) : "l"(a), "l"(b), "l"(c));
    return d;
}

__device__ __forceinline__ float gelu_tanh(float v) {
    float c = 0.7978845608028654f * (v + 0.044715f * v * v * v);
    return 0.5f * v * (1.0f + tanhf(c));
}

// ---------------- K1: transpose x[b,f,c,y,x] -> g_val[b,f,y,x,c] (+time_pos), vectorized ----------------
__global__ __launch_bounds__(256) void k_transpose(const float* __restrict__ x,
                                                   const float* __restrict__ tp) {
    __shared__ float tile[32][33];   // [ch_in_tile][x_in_tile]
    int xt = blockIdx.x * 32;
    int ct = blockIdx.y * 32;
    int z  = blockIdx.z;
    int y  = z & 127;
    int bf = z >> 7;
    int f  = bf & 3;
    int tid = threadIdx.x;

    // load: c = tid>>3 (0..31), xq = tid&7; float4 along x
    {
        int c = tid >> 3, xq = tid & 7;
        const float4 v = *(const float4*)&x[((size_t)(bf * CHN + ct + c) * 128 + y) * 128 + xt + xq * 4];
        tile[c][xq * 4 + 0] = v.x;
        tile[c][xq * 4 + 1] = v.y;
        tile[c][xq * 4 + 2] = v.z;
        tile[c][xq * 4 + 3] = v.w;
    }
    __syncthreads();
    // store: row = tid>>3 .. but need 32 rows: each thread does 4 rows? No: row = tid>>3 covers 0..31 ✓
    {
        int row = tid >> 3, quad = tid & 7;
        const float4 tq = *(const float4*)&tp[f * CHN + ct + quad * 4];
        float4 o;
        o.x = tile[quad * 4 + 0][row] + tq.x;
        o.y = tile[quad * 4 + 1][row] + tq.y;
        o.z = tile[quad * 4 + 2][row] + tq.z;
        o.w = tile[quad * 4 + 3][row] + tq.w;
        *(float4*)&g_val[((size_t)(bf * 128 + y) * 128 + xt + row) * CHN + ct + quad * 4] = o;
    }
}

// ---------------- K2a: channel-max score -> orderable keys ----------------
__global__ __launch_bounds__(1024) void k_score(const float* __restrict__ hm) {
    int i = blockIdx.x * 1024 + threadIdx.x;
    int b = i >> 14, cell = i & (HWSZ - 1);
    const float* hb = hm + (size_t)b * 10 * HWSZ + cell;
    float m = hb[0];
    #pragma unroll
    for (int c = 1; c < 10; c++) m = fmaxf(m, hb[c * HWSZ]);
    unsigned u = __float_as_uint(m);
    u = (u & 0x80000000u) ? ~u : (u | 0x80000000u);
    g_keys[i] = u;
}

// ---------------- K2b: radix top-1024 per batch (parallel suffix-scan select) ----------------
__global__ __launch_bounds__(1024) void k_topk() {
    int b = blockIdx.x, t = threadIdx.x;
    __shared__ unsigned hist[256];
    __shared__ unsigned suf[256];
    __shared__ unsigned sh[4];

    unsigned prefix = 0, r = KQ;
    for (int byte = 3; byte >= 0; byte--) {
        if (t < 256) hist[t] = 0;
        __syncthreads();
        int sh8 = byte * 8;
        unsigned pm = (byte == 3) ? 0u : (0xFFFFFFFFu << (8 * (byte + 1)));
        for (int i = t; i < HWSZ; i += 1024) {
            unsigned k = g_keys[b * HWSZ + i];
            if ((k & pm) == (prefix & pm)) atomicAdd(&hist[(k >> sh8) & 255u], 1u);
        }
        __syncthreads();
        if (t < 256) suf[t] = hist[t];
        __syncthreads();
        #pragma unroll
        for (int off = 1; off < 256; off <<= 1) {
            unsigned add = 0;
            if (t < 256 && t + off < 256) add = suf[t + off];
            __syncthreads();
            if (t < 256) suf[t] += add;
            __syncthreads();
        }
        if (t < 256) {
            unsigned nxt = (t == 255) ? 0u : suf[t + 1];
            if (suf[t] >= r && nxt < r) { sh[0] = (unsigned)t; sh[1] = r - nxt; }
        }
        __syncthreads();
        prefix |= sh[0] << sh8;
        r = sh[1];
        __syncthreads();
    }
    unsigned T = prefix;
    if (t == 0) { sh[2] = 0; sh[3] = 0; }
    __syncthreads();
    for (int i = t; i < HWSZ; i += 1024)
        if (g_keys[b * HWSZ + i] > T) atomicAdd(&sh[2], 1u);
    __syncthreads();
    unsigned cgt = sh[2];
    unsigned neq = KQ - cgt;
    __syncthreads();
    if (t == 0) sh[2] = 0;
    __syncthreads();
    for (int i = t; i < HWSZ; i += 1024) {
        unsigned k = g_keys[b * HWSZ + i];
        if (k > T) {
            unsigned s = atomicAdd(&sh[2], 1u);
            g_ind[b * KQ + s] = i;
        } else if (k == T) {
            unsigned e = atomicAdd(&sh[3], 1u);
            if (e < neq) g_ind[b * KQ + cgt + e] = i;
        }
    }
}

// ---------------- K3: query-init MLP + positional embed gather (2 q/block, grid 1024) ----------------
__global__ __launch_bounds__(256) void k_qinit(
    const float* __restrict__ preds,
    const float* __restrict__ W1, const float* __restrict__ b1,
    const float* __restrict__ W2, const float* __restrict__ b2,
    const float* __restrict__ rowe, const float* __restrict__ cole) {
    __shared__ float q0S[2][70];
    __shared__ float hidS[2][CHN];
    __shared__ int   indS[2];
    int t = threadIdx.x;
    int qg0 = blockIdx.x * 2;
    if (t < 2) indS[t] = g_ind[qg0 + t];
    __syncthreads();
    for (int idx = t; idx < 2 * 70; idx += 256) {
        int q = idx / 70, j = idx - q * 70;
        int b = (qg0 + q) >> 10;
        q0S[q][j] = preds[(b * 70 + j) * HWSZ + indS[q]];
    }
    #pragma unroll
    for (int q = 0; q < 2; q++) {
        int ind = indS[q];
        int xx = ind & 127, yy = ind >> 7;
        float pv = (t < 128) ? cole[xx * 128 + t] : rowe[yy * 128 + (t - 128)];
        g_qpos[(qg0 + q) * CHN + t] = pv;
    }
    __syncthreads();
    float acc[2] = {0.f, 0.f};
    for (int j = 0; j < 70; j++) {
        float w = W1[j * CHN + t];
        acc[0] += q0S[0][j] * w;
        acc[1] += q0S[1][j] * w;
    }
    float bb = b1[t];
    hidS[0][t] = gelu_tanh(acc[0] + bb);
    hidS[1][t] = gelu_tanh(acc[1] + bb);
    __syncthreads();
    float a2[2] = {0.f, 0.f};
    for (int i = 0; i < CHN; i++) {
        float w = W2[i * CHN + t];
        a2[0] += hidS[0][i] * w;
        a2[1] += hidS[1][i] * w;
    }
    float b2v = b2[t];
    g_q[(qg0 + 0) * CHN + t] = a2[0] + b2v;
    g_q[(qg0 + 1) * CHN + t] = a2[1] + b2v;
}

// ---------------- K4: standalone so/aw (layer 0 only) ----------------
__global__ __launch_bounds__(384) void k_soaw(
    const float* __restrict__ soW, const float* __restrict__ sob,
    const float* __restrict__ awW, const float* __restrict__ awb) {
    __shared__ __align__(16) float qnT[256 * TSB];
    int t = threadIdx.x;
    int qg0 = blockIdx.x * 8;

    for (int idx = t; idx < 2048; idx += 384) {
        int q = idx & 7, i = idx >> 3;
        qnT[i * TSB + q] = g_q[(qg0 + q) * CHN + i] + g_qpos[(qg0 + q) * CHN + i];
    }
    __syncthreads();

    if (t < 256) {
        ull acc2[4];
        #pragma unroll
        for (int p = 0; p < 4; p++) acc2[p] = pk2(0.f, 0.f);
        #pragma unroll 4
        for (int i = 0; i < 256; i++) {
            float w = soW[i * CHN + t];
            ull w2 = pk2(w, w);
            const ulonglong2 A0 = *(const ulonglong2*)&qnT[i * TSB + 0];
            const ulonglong2 A1 = *(const ulonglong2*)&qnT[i * TSB + 4];
            acc2[0] = fma2(A0.x, w2, acc2[0]);
            acc2[1] = fma2(A0.y, w2, acc2[1]);
            acc2[2] = fma2(A1.x, w2, acc2[2]);
            acc2[3] = fma2(A1.y, w2, acc2[3]);
        }
        float sbv = sob[t];
        #pragma unroll
        for (int p = 0; p < 4; p++) {
            float lo, hi;
            upk2(acc2[p], lo, hi);
            g_so[(qg0 + 2 * p) * CHN + t]     = lo + sbv;
            g_so[(qg0 + 2 * p + 1) * CHN + t] = hi + sbv;
        }
    } else {
        int c = t - 256;
        ull acc2[4];
        #pragma unroll
        for (int p = 0; p < 4; p++) acc2[p] = pk2(0.f, 0.f);
        #pragma unroll 4
        for (int i = 0; i < 256; i++) {
            float w = awW[i * 128 + c];
            ull w2 = pk2(w, w);
            const ulonglong2 A0 = *(const ulonglong2*)&qnT[i * TSB + 0];
            const ulonglong2 A1 = *(const ulonglong2*)&qnT[i * TSB + 4];
            acc2[0] = fma2(A0.x, w2, acc2[0]);
            acc2[1] = fma2(A0.y, w2, acc2[1]);
            acc2[2] = fma2(A1.x, w2, acc2[2]);
            acc2[3] = fma2(A1.y, w2, acc2[3]);
        }
        float ab = awb[c];
        float av[8];
        #pragma unroll
        for (int p = 0; p < 4; p++) {
            upk2(acc2[p], av[2 * p], av[2 * p + 1]);
            av[2 * p] += ab; av[2 * p + 1] += ab;
        }
        #pragma unroll
        for (int q = 0; q < 8; q++) {
            float vv = av[q];
            float m = vv;
            #pragma unroll
            for (int o = 8; o > 0; o >>= 1)
                m = fmaxf(m, __shfl_xor_sync(0xffffffffu, m, o, 16));
            float e = expf(vv - m);
            float s = e;
            #pragma unroll
            for (int o = 8; o > 0; o >>= 1)
                s += __shfl_xor_sync(0xffffffffu, s, o, 16);
            g_aw[(qg0 + q) * 128 + c] = e / s;
        }
    }
}

// ---------------- K5: per-query dedup gather-aggregate (1 query / block) ----------------
__global__ __launch_bounds__(256) void k_gather() {
    __shared__ __align__(16) float hcoef[HSLOTS * 8];
    __shared__ __align__(16) float coefC[HSLOTS * 8];
    __shared__ int hkey[HSLOTS];
    __shared__ int cellList[HSLOTS];
    __shared__ int cntS;

    int t = threadIdx.x;
    int kq = blockIdx.x;
    int b = kq >> 10;

    hkey[t] = -1;
    ((float4*)hcoef)[t * 2]     = make_float4(0.f, 0.f, 0.f, 0.f);
    ((float4*)hcoef)[t * 2 + 1] = make_float4(0.f, 0.f, 0.f, 0.f);
    if (t == 0) cntS = 0;
    __syncthreads();

    if (t < 128) {
        int ind = g_ind[kq];
        int h = t >> 4;
        int f = (t >> 2) & 3;
        float offx = g_so[kq * CHN + 2 * t];
        float offy = g_so[kq * CHN + 2 * t + 1];
        float aw = g_aw[kq * 128 + t];
        float xs = (float)(ind & 127) + offx;
        float ys = (float)(ind >> 7) + offy;
        float xf = floorf(xs), yf = floorf(ys);
        int x0 = (int)xf, y0 = (int)yf;
        float wx1 = xs - xf, wy1 = ys - yf;
        float wx0 = 1.f - wx1, wy0 = 1.f - wy1;
        int cxs[4] = {x0, x0 + 1, x0, x0 + 1};
        int cys[4] = {y0, y0, y0 + 1, y0 + 1};
        float cw[4] = {wx0 * wy0, wx1 * wy0, wx0 * wy1, wx1 * wy1};
        int base = (b * 4 + f) * HWSZ;
        float evs = 0.f;
        #pragma unroll
        for (int c = 0; c < 4; c++) {
            bool v = (cxs[c] >= 0) & (cxs[c] < 128) & (cys[c] >= 0) & (cys[c] < 128);
            if (v) {
                int key = base + cys[c] * 128 + cxs[c];
                float cf = aw * cw[c];
                evs += cf;
                unsigned s = ((unsigned)key * 2654435761u) >> 24;
                while (true) {
                    int prev = atomicCAS(&hkey[s], -1, key);
                    if (prev == -1 || prev == key) break;
                    s = (s + 1) & (HSLOTS - 1);
                }
                atomicAdd(&hcoef[s * 8 + h], cf);
            }
        }
        #pragma unroll
        for (int o = 8; o > 0; o >>= 1)
            evs += __shfl_xor_sync(0xffffffffu, evs, o, 16);
        if ((t & 15) == 0) g_bw[kq * 8 + h] = evs;
    }
    __syncthreads();

    {
        int key = hkey[t];
        if (key >= 0) {
            int pos = atomicAdd(&cntS, 1);
            cellList[pos] = key;
            ((float4*)coefC)[pos * 2]     = ((const float4*)hcoef)[t * 2];
            ((float4*)coefC)[pos * 2 + 1] = ((const float4*)hcoef)[t * 2 + 1];
        }
    }
    __syncthreads();
    int D = cntS;

    ull acc2[4];
    #pragma unroll
    for (int p = 0; p < 4; p++) acc2[p] = pk2(0.f, 0.f);
    int d = 0;
    for (; d + 4 <= D; d += 4) {
        float v0 = g_val[(size_t)cellList[d + 0] * CHN + t];
        float v1 = g_val[(size_t)cellList[d + 1] * CHN + t];
        float v2 = g_val[(size_t)cellList[d + 2] * CHN + t];
        float v3 = g_val[(size_t)cellList[d + 3] * CHN + t];
        #pragma unroll
        for (int u = 0; u < 4; u++) {
            float vv = (u == 0) ? v0 : (u == 1) ? v1 : (u == 2) ? v2 : v3;
            ull v2p = pk2(vv, vv);
            const ulonglong2 C0 = *(const ulonglong2*)&coefC[(d + u) * 8];
            const ulonglong2 C1 = *(const ulonglong2*)&coefC[(d + u) * 8 + 4];
            acc2[0] = fma2(C0.x, v2p, acc2[0]);
            acc2[1] = fma2(C0.y, v2p, acc2[1]);
            acc2[2] = fma2(C1.x, v2p, acc2[2]);
            acc2[3] = fma2(C1.y, v2p, acc2[3]);
        }
    }
    for (; d < D; d++) {
        float vv = g_val[(size_t)cellList[d] * CHN + t];
        ull v2p = pk2(vv, vv);
        const ulonglong2 C0 = *(const ulonglong2*)&coefC[d * 8];
        const ulonglong2 C1 = *(const ulonglong2*)&coefC[d * 8 + 4];
        acc2[0] = fma2(C0.x, v2p, acc2[0]);
        acc2[1] = fma2(C0.y, v2p, acc2[1]);
        acc2[2] = fma2(C1.x, v2p, acc2[2]);
        acc2[3] = fma2(C1.y, v2p, acc2[3]);
    }
    #pragma unroll
    for (int p = 0; p < 4; p++) {
        float lo, hi;
        upk2(acc2[p], lo, hi);
        g_agg[((size_t)kq * 8 + 2 * p) * CHN + t]     = lo;
        g_agg[((size_t)kq * 8 + 2 * p + 1) * CHN + t] = hi;
    }
}

// ---------------- K6: per-layer tail + fused next-layer soaw ----------------
__device__ __forceinline__ void ln4h(float v[4], float* redA, float* redB,
                                     float* mu, float* rs,
                                     const float* g, const float* b,
                                     int ch, int grp, int t) {
    int w = (t >> 5) & 7;
    int ln = t & 31;
    #pragma unroll
    for (int q = 0; q < 4; q++) {
        float s = v[q], s2 = v[q] * v[q];
        #pragma unroll
        for (int o = 16; o > 0; o >>= 1) {
            s  += __shfl_xor_sync(0xffffffffu, s, o);
            s2 += __shfl_xor_sync(0xffffffffu, s2, o);
        }
        if (ln == 0) { redA[(grp * 4 + q) * 8 + w] = s; redB[(grp * 4 + q) * 8 + w] = s2; }
    }
    __syncthreads();
    if (t < 8) {
        float s = 0.f, s2 = 0.f;
        #pragma unroll
        for (int k = 0; k < 8; k++) { s += redA[t * 8 + k]; s2 += redB[t * 8 + k]; }
        float m = s * (1.f / 256.f);
        mu[t] = m;
        rs[t] = rsqrtf(s2 * (1.f / 256.f) - m * m + 1e-5f);
    }
    __syncthreads();
    float gg = g[ch], bb = b[ch];
    #pragma unroll
    for (int q = 0; q < 4; q++)
        v[q] = (v[q] - mu[grp * 4 + q]) * rs[grp * 4 + q] * gg + bb;
}

__global__ __launch_bounds__(512) void k_tail(
    const float* __restrict__ vpW, const float* __restrict__ vpb,
    const float* __restrict__ opW, const float* __restrict__ opb,
    const float* __restrict__ g1, const float* __restrict__ b1,
    const float* __restrict__ W1, const float* __restrict__ fb1,
    const float* __restrict__ W2, const float* __restrict__ fb2,
    const float* __restrict__ g2, const float* __restrict__ b2,
    const float* __restrict__ soWn, const float* __restrict__ sobn,
    const float* __restrict__ awWn, const float* __restrict__ awbn,
    int has_next) {
    __shared__ __align__(16) float bufT[256 * TSB];
    __shared__ __align__(16) float qST[256 * TSB];
    __shared__ float redA[8 * 8], redB[8 * 8];
    __shared__ float mu[8], rs[8];
    int t = threadIdx.x;
    int ch = t & 255;
    int grp = t >> 8;
    int qb = grp * 4;
    int qg0 = blockIdx.x * 8;
    int h = ch >> 5;

    float v[4];

    // ---- vp: f32x2 over the reduction dim ----
    {
        ull a2v[4];
        #pragma unroll
        for (int q = 0; q < 4; q++) a2v[q] = pk2(0.f, 0.f);
        for (int i4 = 0; i4 < 64; i4++) {
            float w0 = vpW[(4 * i4 + 0) * CHN + ch];
            float w1 = vpW[(4 * i4 + 1) * CHN + ch];
            float w2 = vpW[(4 * i4 + 2) * CHN + ch];
            float w3 = vpW[(4 * i4 + 3) * CHN + ch];
            ull w01 = pk2(w0, w1), w23 = pk2(w2, w3);
            #pragma unroll
            for (int q = 0; q < 4; q++) {
                const ulonglong2 a = *(const ulonglong2*)&g_agg[((size_t)(qg0 + qb + q) * 8 + h) * CHN + 4 * i4];
                a2v[q] = fma2(a.x, w01, a2v[q]);
                a2v[q] = fma2(a.y, w23, a2v[q]);
            }
        }
        float vb = vpb[ch];
        float4 o;
        float lo, hi;
        upk2(a2v[0], lo, hi); o.x = lo + hi + g_bw[(qg0 + qb + 0) * 8 + h] * vb;
        upk2(a2v[1], lo, hi); o.y = lo + hi + g_bw[(qg0 + qb + 1) * 8 + h] * vb;
        upk2(a2v[2], lo, hi); o.z = lo + hi + g_bw[(qg0 + qb + 2) * 8 + h] * vb;
        upk2(a2v[3], lo, hi); o.w = lo + hi + g_bw[(qg0 + qb + 3) * 8 + h] * vb;
        *(float4*)&bufT[ch * TSB + qb] = o;
    }
    __syncthreads();

    // ---- op ----
    ull acc2[2];
    acc2[0] = pk2(g_q[(qg0 + qb + 0) * CHN + ch], g_q[(qg0 + qb + 1) * CHN + ch]);
    acc2[1] = pk2(g_q[(qg0 + qb + 2) * CHN + ch], g_q[(qg0 + qb + 3) * CHN + ch]);
    #pragma unroll 4
    for (int i = 0; i < 256; i++) {
        float w = opW[i * CHN + ch];
        ull w2 = pk2(w, w);
        const ulonglong2 A0 = *(const ulonglong2*)&bufT[i * TSB + qb];
        acc2[0] = fma2(A0.x, w2, acc2[0]);
        acc2[1] = fma2(A0.y, w2, acc2[1]);
    }
    {
        float ob = opb[ch];
        upk2(acc2[0], v[0], v[1]);
        upk2(acc2[1], v[2], v[3]);
        #pragma unroll
        for (int q = 0; q < 4; q++) v[q] += ob;
    }

    // ---- LN1 ----
    ln4h(v, redA, redB, mu, rs, g1, b1, ch, grp, t);
    *(float4*)&qST[ch * TSB + qb] = make_float4(v[0], v[1], v[2], v[3]);
    __syncthreads();

    // ---- FFN ----
    ull o2[2];
    o2[0] = pk2(0.f, 0.f); o2[1] = pk2(0.f, 0.f);
    for (int chunk = 0; chunk < 4; chunk++) {
        ull h2[2];
        h2[0] = pk2(0.f, 0.f); h2[1] = pk2(0.f, 0.f);
        int j = chunk * CHN + ch;
        #pragma unroll 4
        for (int i = 0; i < 256; i++) {
            float w = W1[i * 1024 + j];
            ull w2 = pk2(w, w);
            const ulonglong2 A0 = *(const ulonglong2*)&qST[i * TSB + qb];
            h2[0] = fma2(A0.x, w2, h2[0]);
            h2[1] = fma2(A0.y, w2, h2[1]);
        }
        float bj = fb1[j];
        {
            float a, b_, c, d_;
            upk2(h2[0], a, b_);
            upk2(h2[1], c, d_);
            *(float4*)&bufT[ch * TSB + qb] = make_float4(
                fmaxf(a + bj, 0.f), fmaxf(b_ + bj, 0.f),
                fmaxf(c + bj, 0.f), fmaxf(d_ + bj, 0.f));
        }
        __syncthreads();
        #pragma unroll 4
        for (int i = 0; i < 256; i++) {
            float w = W2[(chunk * CHN + i) * CHN + ch];
            ull w2 = pk2(w, w);
            const ulonglong2 A0 = *(const ulonglong2*)&bufT[i * TSB + qb];
            o2[0] = fma2(A0.x, w2, o2[0]);
            o2[1] = fma2(A0.y, w2, o2[1]);
        }
        __syncthreads();
    }
    {
        float fb = fb2[ch];
        upk2(o2[0], v[0], v[1]);
        upk2(o2[1], v[2], v[3]);
        #pragma unroll
        for (int q = 0; q < 4; q++) v[q] += qST[ch * TSB + qb + q] + fb;
    }

    // ---- LN2 ----
    ln4h(v, redA, redB, mu, rs, g2, b2, ch, grp, t);
    #pragma unroll
    for (int q = 0; q < 4; q++) g_q[(qg0 + qb + q) * CHN + ch] = v[q];

    // ---- fused next-layer so/aw: qn = LN2 out + qpos, reuse bufT ----
    if (has_next) {
        #pragma unroll
        for (int q = 0; q < 4; q++)
            bufT[ch * TSB + qb + q] = v[q] + g_qpos[(qg0 + qb + q) * CHN + ch];
        __syncthreads();

        if (t < 256) {
            ull s2[4];
            #pragma unroll
            for (int p = 0; p < 4; p++) s2[p] = pk2(0.f, 0.f);
            #pragma unroll 4
            for (int i = 0; i < 256; i++) {
                float w = soWn[i * CHN + t];
                ull w2 = pk2(w, w);
                const ulonglong2 A0 = *(const ulonglong2*)&bufT[i * TSB + 0];
                const ulonglong2 A1 = *(const ulonglong2*)&bufT[i * TSB + 4];
                s2[0] = fma2(A0.x, w2, s2[0]);
                s2[1] = fma2(A0.y, w2, s2[1]);
                s2[2] = fma2(A1.x, w2, s2[2]);
                s2[3] = fma2(A1.y, w2, s2[3]);
            }
            float sbv = sobn[t];
            #pragma unroll
            for (int p = 0; p < 4; p++) {
                float lo, hi;
                upk2(s2[p], lo, hi);
                g_so[(qg0 + 2 * p) * CHN + t]     = lo + sbv;
                g_so[(qg0 + 2 * p + 1) * CHN + t] = hi + sbv;
            }
        } else if (t < 384) {
            int c = t - 256;
            ull s2[4];
            #pragma unroll
            for (int p = 0; p < 4; p++) s2[p] = pk2(0.f, 0.f);
            #pragma unroll 4
            for (int i = 0; i < 256; i++) {
                float w = awWn[i * 128 + c];
                ull w2 = pk2(w, w);
                const ulonglong2 A0 = *(const ulonglong2*)&bufT[i * TSB + 0];
                const ulonglong2 A1 = *(const ulonglong2*)&bufT[i * TSB + 4];
                s2[0] = fma2(A0.x, w2, s2[0]);
                s2[1] = fma2(A0.y, w2, s2[1]);
                s2[2] = fma2(A1.x, w2, s2[2]);
                s2[3] = fma2(A1.y, w2, s2[3]);
            }
            float ab = awbn[c];
            float av[8];
            #pragma unroll
            for (int p = 0; p < 4; p++) {
                upk2(s2[p], av[2 * p], av[2 * p + 1]);
                av[2 * p] += ab; av[2 * p + 1] += ab;
            }
            #pragma unroll
            for (int q = 0; q < 8; q++) {
                float vv = av[q];
                float m = vv;
                #pragma unroll
                for (int o = 8; o > 0; o >>= 1)
                    m = fmaxf(m, __shfl_xor_sync(0xffffffffu, m, o, 16));
                float e = expf(vv - m);
                float s = e;
                #pragma unroll
                for (int o = 8; o > 0; o >>= 1)
                    s += __shfl_xor_sync(0xffffffffu, s, o, 16);
                g_aw[(qg0 + q) * 128 + c] = e / s;
            }
        }
    }
}

// ---------------- K7/K8: zero-fill output, scatter queries ----------------
__global__ void k_zero(float4* __restrict__ out) {
    out[(size_t)blockIdx.x * 256 + threadIdx.x] = make_float4(0.f, 0.f, 0.f, 0.f);
}

__global__ void k_scatter(float* __restrict__ out) {
    int k = blockIdx.x, t = threadIdx.x;
    int b = k >> 10;
    int ind = g_ind[k];
    out[(b * CHN + t) * HWSZ + ind] = g_q[k * CHN + t];
}

// ---------------- launch (single stream) ----------------
extern "C" void kernel_launch(void* const* d_in, const int* in_sizes, int n_in,
                              void* d_out, int out_size) {
    const float* x    = (const float*)d_in[0];
    const float* preds= (const float*)d_in[1];
    const float* hm   = (const float*)d_in[2];
    const float* mW1  = (const float*)d_in[3];
    const float* mb1  = (const float*)d_in[4];
    const float* mW2  = (const float*)d_in[5];
    const float* mb2  = (const float*)d_in[6];
    const float* tp   = (const float*)d_in[7];
    const float* rowe = (const float*)d_in[8];
    const float* cole = (const float*)d_in[9];
    const float* soW  = (const float*)d_in[10];
    const float* sob  = (const float*)d_in[11];
    const float* awW  = (const float*)d_in[12];
    const float* awb  = (const float*)d_in[13];
    const float* vpW  = (const float*)d_in[14];
    const float* vpb  = (const float*)d_in[15];
    const float* opW  = (const float*)d_in[16];
    const float* opb  = (const float*)d_in[17];
    const float* l1g  = (const float*)d_in[18];
    const float* l1b  = (const float*)d_in[19];
    const float* fW1  = (const float*)d_in[20];
    const float* fb1  = (const float*)d_in[21];
    const float* fW2  = (const float*)d_in[22];
    const float* fb2  = (const float*)d_in[23];
    const float* l2g  = (const float*)d_in[24];
    const float* l2b  = (const float*)d_in[25];
    float* out = (float*)d_out;

    k_transpose<<<dim3(4, 8, 1024), 256>>>(x, tp);
    k_score<<<32, 1024>>>(hm);
    k_topk<<<2, 1024>>>();
    k_qinit<<<1024, 256>>>(preds, mW1, mb1, mW2, mb2, rowe, cole);
    k_soaw<<<256, 384>>>(soW, sob, awW, awb);
    for (int l = 0; l < 3; l++) {
        int nl = l + 1;
        k_gather<<<2048, 256>>>();
        k_tail<<<256, 512>>>(vpW + l * 65536, vpb + l * 256,
                             opW + l * 65536, opb + l * 256,
                             l1g + l * 256, l1b + l * 256,
                             fW1 + l * 262144, fb1 + l * 1024,
                             fW2 + l * 262144, fb2 + l * 256,
                             l2g + l * 256, l2b + l * 256,
                             soW + nl * 65536, sob + nl * 256,
                             awW + nl * 32768, awb + nl * 128,
                             (l < 2) ? 1 : 0);
    }
    k_zero<<<8192, 256>>>((float4*)out);
    k_scatter<<<2048, 256>>>(out);
}

// round 14
// speedup vs baseline: 1.1614x; 1.0016x over previous
#include <cuda_runtime.h>
#include <cuda_fp16.h>
#include <math.h>

#define HWSZ 16384
#define CHN  256
#define KQ   1024
#define NQ   2048
#define HSLOTS 256
#define TSB 12   // transposed activation stride (8 q + 4 pad), 48B = 16B-aligned rows

// ---------------- device scratch (static, allocation-free) ----------------
__device__ unsigned short g_val[(size_t)2 * 4 * HWSZ * CHN];  // fp16 [b*4+f][y][x][c], +time_pos
__device__ unsigned g_keys[2 * HWSZ];
__device__ int      g_ind[NQ];
__device__ float    g_q[NQ * CHN];
__device__ float    g_qpos[NQ * CHN];
__device__ float    g_so[NQ * CHN];
__device__ float    g_aw[NQ * 128];
__device__ float    g_agg[(size_t)NQ * 8 * CHN];   // [q][h][ch]
__device__ float    g_bw[NQ * 8];

// ---------------- f32x2 packed helpers ----------------
typedef unsigned long long ull;
__device__ __forceinline__ ull pk2(float x, float y) {
    ull r;
    asm("mov.b64 %0, {%1, %2};" : "=l"(r) : "f"(x), "f"(y));
    return r;
}
__device__ __forceinline__ void upk2(ull v, float& x, float& y) {
    asm("mov.b64 {%0, %1}, %2;" : "=f"(x), "=f"(y) : "l"(v));
}
__device__ __forceinline__ ull fma2(ull a, ull b, ull c) {
    ull d;
    asm("fma.rn.f32x2 %0, %1, %2, %3;" : "=l"(d) : "l"(a), "l"(b), "l"(c));
    return d;
}
// pack two floats into fp16x2 (lo = a, hi = b)
__device__ __forceinline__ unsigned h2pack(float a, float b) {
    __half2 h = __floats2half2_rn(a, b);
    return *(unsigned*)&h;
}
__device__ __forceinline__ float h2f(unsigned short r) {
    __half h = *(__half*)&r;
    return __half2float(h);
}

__device__ __forceinline__ float gelu_tanh(float v) {
    float c = 0.7978845608028654f * (v + 0.044715f * v * v * v);
    return 0.5f * v * (1.0f + tanhf(c));
}

// ---------------- K1: transpose x[b,f,c,y,x] -> g_val[b,f,y,x,c] fp16 (+time_pos) ----------------
__global__ __launch_bounds__(256) void k_transpose(const float* __restrict__ x,
                                                   const float* __restrict__ tp) {
    __shared__ float tile[32][33];   // [ch_in_tile][x_in_tile]
    int xt = blockIdx.x * 32;
    int ct = blockIdx.y * 32;
    int z  = blockIdx.z;
    int y  = z & 127;
    int bf = z >> 7;
    int f  = bf & 3;
    int tid = threadIdx.x;

    {
        int c = tid >> 3, xq = tid & 7;
        const float4 v = *(const float4*)&x[((size_t)(bf * CHN + ct + c) * 128 + y) * 128 + xt + xq * 4];
        tile[c][xq * 4 + 0] = v.x;
        tile[c][xq * 4 + 1] = v.y;
        tile[c][xq * 4 + 2] = v.z;
        tile[c][xq * 4 + 3] = v.w;
    }
    __syncthreads();
    {
        int row = tid >> 3, quad = tid & 7;
        const float4 tq = *(const float4*)&tp[f * CHN + ct + quad * 4];
        float o0 = tile[quad * 4 + 0][row] + tq.x;
        float o1 = tile[quad * 4 + 1][row] + tq.y;
        float o2 = tile[quad * 4 + 2][row] + tq.z;
        float o3 = tile[quad * 4 + 3][row] + tq.w;
        uint2 packed = make_uint2(h2pack(o0, o1), h2pack(o2, o3));
        *(uint2*)&g_val[((size_t)(bf * 128 + y) * 128 + xt + row) * CHN + ct + quad * 4] = packed;
    }
}

// ---------------- K2a: channel-max score -> orderable keys ----------------
__global__ __launch_bounds__(1024) void k_score(const float* __restrict__ hm) {
    int i = blockIdx.x * 1024 + threadIdx.x;
    int b = i >> 14, cell = i & (HWSZ - 1);
    const float* hb = hm + (size_t)b * 10 * HWSZ + cell;
    float m = hb[0];
    #pragma unroll
    for (int c = 1; c < 10; c++) m = fmaxf(m, hb[c * HWSZ]);
    unsigned u = __float_as_uint(m);
    u = (u & 0x80000000u) ? ~u : (u | 0x80000000u);
    g_keys[i] = u;
}

// ---------------- K2b: radix top-1024 per batch (parallel suffix-scan select) ----------------
__global__ __launch_bounds__(1024) void k_topk() {
    int b = blockIdx.x, t = threadIdx.x;
    __shared__ unsigned hist[256];
    __shared__ unsigned suf[256];
    __shared__ unsigned sh[4];

    unsigned prefix = 0, r = KQ;
    for (int byte = 3; byte >= 0; byte--) {
        if (t < 256) hist[t] = 0;
        __syncthreads();
        int sh8 = byte * 8;
        unsigned pm = (byte == 3) ? 0u : (0xFFFFFFFFu << (8 * (byte + 1)));
        for (int i = t; i < HWSZ; i += 1024) {
            unsigned k = g_keys[b * HWSZ + i];
            if ((k & pm) == (prefix & pm)) atomicAdd(&hist[(k >> sh8) & 255u], 1u);
        }
        __syncthreads();
        if (t < 256) suf[t] = hist[t];
        __syncthreads();
        #pragma unroll
        for (int off = 1; off < 256; off <<= 1) {
            unsigned add = 0;
            if (t < 256 && t + off < 256) add = suf[t + off];
            __syncthreads();
            if (t < 256) suf[t] += add;
            __syncthreads();
        }
        if (t < 256) {
            unsigned nxt = (t == 255) ? 0u : suf[t + 1];
            if (suf[t] >= r && nxt < r) { sh[0] = (unsigned)t; sh[1] = r - nxt; }
        }
        __syncthreads();
        prefix |= sh[0] << sh8;
        r = sh[1];
        __syncthreads();
    }
    unsigned T = prefix;
    if (t == 0) { sh[2] = 0; sh[3] = 0; }
    __syncthreads();
    for (int i = t; i < HWSZ; i += 1024)
        if (g_keys[b * HWSZ + i] > T) atomicAdd(&sh[2], 1u);
    __syncthreads();
    unsigned cgt = sh[2];
    unsigned neq = KQ - cgt;
    __syncthreads();
    if (t == 0) sh[2] = 0;
    __syncthreads();
    for (int i = t; i < HWSZ; i += 1024) {
        unsigned k = g_keys[b * HWSZ + i];
        if (k > T) {
            unsigned s = atomicAdd(&sh[2], 1u);
            g_ind[b * KQ + s] = i;
        } else if (k == T) {
            unsigned e = atomicAdd(&sh[3], 1u);
            if (e < neq) g_ind[b * KQ + cgt + e] = i;
        }
    }
}

// ---------------- K3: query-init MLP + positional embed gather (2 q/block, f32x2) ----------------
__global__ __launch_bounds__(256) void k_qinit(
    const float* __restrict__ preds,
    const float* __restrict__ W1, const float* __restrict__ b1,
    const float* __restrict__ W2, const float* __restrict__ b2,
    const float* __restrict__ rowe, const float* __restrict__ cole) {
    __shared__ __align__(8) float2 qpair[70];    // [j] -> (q0, q1)
    __shared__ __align__(8) float2 hid2[CHN];    // [i] -> (q0, q1)
    __shared__ int indS[2];
    int t = threadIdx.x;
    int qg0 = blockIdx.x * 2;
    if (t < 2) indS[t] = g_ind[qg0 + t];
    __syncthreads();
    for (int idx = t; idx < 140; idx += 256) {
        int j = idx >> 1, q = idx & 1;
        int b = (qg0 + q) >> 10;
        ((float*)qpair)[j * 2 + q] = preds[(b * 70 + j) * HWSZ + indS[q]];
    }
    #pragma unroll
    for (int q = 0; q < 2; q++) {
        int ind = indS[q];
        int xx = ind & 127, yy = ind >> 7;
        float pv = (t < 128) ? cole[xx * 128 + t] : rowe[yy * 128 + (t - 128)];
        g_qpos[(qg0 + q) * CHN + t] = pv;
    }
    __syncthreads();
    ull acc = pk2(0.f, 0.f);
    for (int j = 0; j < 70; j++) {
        float w = W1[j * CHN + t];
        acc = fma2(*(const ull*)&qpair[j], pk2(w, w), acc);
    }
    float bb = b1[t];
    {
        float a0, a1;
        upk2(acc, a0, a1);
        hid2[t] = make_float2(gelu_tanh(a0 + bb), gelu_tanh(a1 + bb));
    }
    __syncthreads();
    ull a2 = pk2(0.f, 0.f);
    #pragma unroll 4
    for (int i = 0; i < CHN; i++) {
        float w = W2[i * CHN + t];
        a2 = fma2(*(const ull*)&hid2[i], pk2(w, w), a2);
    }
    float b2v = b2[t];
    float o0, o1;
    upk2(a2, o0, o1);
    g_q[(qg0 + 0) * CHN + t] = o0 + b2v;
    g_q[(qg0 + 1) * CHN + t] = o1 + b2v;
}

// ---------------- K4: standalone so/aw (layer 0 only) ----------------
__global__ __launch_bounds__(384) void k_soaw(
    const float* __restrict__ soW, const float* __restrict__ sob,
    const float* __restrict__ awW, const float* __restrict__ awb) {
    __shared__ __align__(16) float qnT[256 * TSB];
    int t = threadIdx.x;
    int qg0 = blockIdx.x * 8;

    for (int idx = t; idx < 2048; idx += 384) {
        int q = idx & 7, i = idx >> 3;
        qnT[i * TSB + q] = g_q[(qg0 + q) * CHN + i] + g_qpos[(qg0 + q) * CHN + i];
    }
    __syncthreads();

    if (t < 256) {
        ull acc2[4];
        #pragma unroll
        for (int p = 0; p < 4; p++) acc2[p] = pk2(0.f, 0.f);
        #pragma unroll 4
        for (int i = 0; i < 256; i++) {
            float w = soW[i * CHN + t];
            ull w2 = pk2(w, w);
            const ulonglong2 A0 = *(const ulonglong2*)&qnT[i * TSB + 0];
            const ulonglong2 A1 = *(const ulonglong2*)&qnT[i * TSB + 4];
            acc2[0] = fma2(A0.x, w2, acc2[0]);
            acc2[1] = fma2(A0.y, w2, acc2[1]);
            acc2[2] = fma2(A1.x, w2, acc2[2]);
            acc2[3] = fma2(A1.y, w2, acc2[3]);
        }
        float sbv = sob[t];
        #pragma unroll
        for (int p = 0; p < 4; p++) {
            float lo, hi;
            upk2(acc2[p], lo, hi);
            g_so[(qg0 + 2 * p) * CHN + t]     = lo + sbv;
            g_so[(qg0 + 2 * p + 1) * CHN + t] = hi + sbv;
        }
    } else {
        int c = t - 256;
        ull acc2[4];
        #pragma unroll
        for (int p = 0; p < 4; p++) acc2[p] = pk2(0.f, 0.f);
        #pragma unroll 4
        for (int i = 0; i < 256; i++) {
            float w = awW[i * 128 + c];
            ull w2 = pk2(w, w);
            const ulonglong2 A0 = *(const ulonglong2*)&qnT[i * TSB + 0];
            const ulonglong2 A1 = *(const ulonglong2*)&qnT[i * TSB + 4];
            acc2[0] = fma2(A0.x, w2, acc2[0]);
            acc2[1] = fma2(A0.y, w2, acc2[1]);
            acc2[2] = fma2(A1.x, w2, acc2[2]);
            acc2[3] = fma2(A1.y, w2, acc2[3]);
        }
        float ab = awb[c];
        float av[8];
        #pragma unroll
        for (int p = 0; p < 4; p++) {
            upk2(acc2[p], av[2 * p], av[2 * p + 1]);
            av[2 * p] += ab; av[2 * p + 1] += ab;
        }
        #pragma unroll
        for (int q = 0; q < 8; q++) {
            float vv = av[q];
            float m = vv;
            #pragma unroll
            for (int o = 8; o > 0; o >>= 1)
                m = fmaxf(m, __shfl_xor_sync(0xffffffffu, m, o, 16));
            float e = expf(vv - m);
            float s = e;
            #pragma unroll
            for (int o = 8; o > 0; o >>= 1)
                s += __shfl_xor_sync(0xffffffffu, s, o, 16);
            g_aw[(qg0 + q) * 128 + c] = e / s;
        }
    }
}

// ---------------- K5: per-query dedup gather-aggregate (fp16 values) ----------------
__global__ __launch_bounds__(256) void k_gather() {
    __shared__ __align__(16) float hcoef[HSLOTS * 8];
    __shared__ __align__(16) float coefC[HSLOTS * 8];
    __shared__ int hkey[HSLOTS];
    __shared__ int cellList[HSLOTS];
    __shared__ int cntS;

    int t = threadIdx.x;
    int kq = blockIdx.x;
    int b = kq >> 10;

    hkey[t] = -1;
    ((float4*)hcoef)[t * 2]     = make_float4(0.f, 0.f, 0.f, 0.f);
    ((float4*)hcoef)[t * 2 + 1] = make_float4(0.f, 0.f, 0.f, 0.f);
    if (t == 0) cntS = 0;
    __syncthreads();

    if (t < 128) {
        int ind = g_ind[kq];
        int h = t >> 4;
        int f = (t >> 2) & 3;
        float offx = g_so[kq * CHN + 2 * t];
        float offy = g_so[kq * CHN + 2 * t + 1];
        float aw = g_aw[kq * 128 + t];
        float xs = (float)(ind & 127) + offx;
        float ys = (float)(ind >> 7) + offy;
        float xf = floorf(xs), yf = floorf(ys);
        int x0 = (int)xf, y0 = (int)yf;
        float wx1 = xs - xf, wy1 = ys - yf;
        float wx0 = 1.f - wx1, wy0 = 1.f - wy1;
        int cxs[4] = {x0, x0 + 1, x0, x0 + 1};
        int cys[4] = {y0, y0, y0 + 1, y0 + 1};
        float cw[4] = {wx0 * wy0, wx1 * wy0, wx0 * wy1, wx1 * wy1};
        int base = (b * 4 + f) * HWSZ;
        float evs = 0.f;
        #pragma unroll
        for (int c = 0; c < 4; c++) {
            bool v = (cxs[c] >= 0) & (cxs[c] < 128) & (cys[c] >= 0) & (cys[c] < 128);
            if (v) {
                int key = base + cys[c] * 128 + cxs[c];
                float cf = aw * cw[c];
                evs += cf;
                unsigned s = ((unsigned)key * 2654435761u) >> 24;
                while (true) {
                    int prev = atomicCAS(&hkey[s], -1, key);
                    if (prev == -1 || prev == key) break;
                    s = (s + 1) & (HSLOTS - 1);
                }
                atomicAdd(&hcoef[s * 8 + h], cf);
            }
        }
        #pragma unroll
        for (int o = 8; o > 0; o >>= 1)
            evs += __shfl_xor_sync(0xffffffffu, evs, o, 16);
        if ((t & 15) == 0) g_bw[kq * 8 + h] = evs;
    }
    __syncthreads();

    {
        int key = hkey[t];
        if (key >= 0) {
            int pos = atomicAdd(&cntS, 1);
            cellList[pos] = key;
            ((float4*)coefC)[pos * 2]     = ((const float4*)hcoef)[t * 2];
            ((float4*)coefC)[pos * 2 + 1] = ((const float4*)hcoef)[t * 2 + 1];
        }
    }
    __syncthreads();
    int D = cntS;

    // aggregate: thread = channel; fp16 value loads (2B), f32x2 coefs, MLP=4
    ull acc2[4];
    #pragma unroll
    for (int p = 0; p < 4; p++) acc2[p] = pk2(0.f, 0.f);
    int d = 0;
    for (; d + 4 <= D; d += 4) {
        unsigned short r0 = g_val[(size_t)cellList[d + 0] * CHN + t];
        unsigned short r1 = g_val[(size_t)cellList[d + 1] * CHN + t];
        unsigned short r2 = g_val[(size_t)cellList[d + 2] * CHN + t];
        unsigned short r3 = g_val[(size_t)cellList[d + 3] * CHN + t];
        #pragma unroll
        for (int u = 0; u < 4; u++) {
            unsigned short rr = (u == 0) ? r0 : (u == 1) ? r1 : (u == 2) ? r2 : r3;
            float vv = h2f(rr);
            ull v2p = pk2(vv, vv);
            const ulonglong2 C0 = *(const ulonglong2*)&coefC[(d + u) * 8];
            const ulonglong2 C1 = *(const ulonglong2*)&coefC[(d + u) * 8 + 4];
            acc2[0] = fma2(C0.x, v2p, acc2[0]);
            acc2[1] = fma2(C0.y, v2p, acc2[1]);
            acc2[2] = fma2(C1.x, v2p, acc2[2]);
            acc2[3] = fma2(C1.y, v2p, acc2[3]);
        }
    }
    for (; d < D; d++) {
        unsigned short rr = g_val[(size_t)cellList[d] * CHN + t];
        float vv = h2f(rr);
        ull v2p = pk2(vv, vv);
        const ulonglong2 C0 = *(const ulonglong2*)&coefC[d * 8];
        const ulonglong2 C1 = *(const ulonglong2*)&coefC[d * 8 + 4];
        acc2[0] = fma2(C0.x, v2p, acc2[0]);
        acc2[1] = fma2(C0.y, v2p, acc2[1]);
        acc2[2] = fma2(C1.x, v2p, acc2[2]);
        acc2[3] = fma2(C1.y, v2p, acc2[3]);
    }
    #pragma unroll
    for (int p = 0; p < 4; p++) {
        float lo, hi;
        upk2(acc2[p], lo, hi);
        g_agg[((size_t)kq * 8 + 2 * p) * CHN + t]     = lo;
        g_agg[((size_t)kq * 8 + 2 * p + 1) * CHN + t] = hi;
    }
}

// ---------------- K6: per-layer tail + fused next-layer soaw ----------------
__device__ __forceinline__ void ln4h(float v[4], float* redA, float* redB,
                                     float* mu, float* rs,
                                     const float* g, const float* b,
                                     int ch, int grp, int t) {
    int w = (t >> 5) & 7;
    int ln = t & 31;
    #pragma unroll
    for (int q = 0; q < 4; q++) {
        float s = v[q], s2 = v[q] * v[q];
        #pragma unroll
        for (int o = 16; o > 0; o >>= 1) {
            s  += __shfl_xor_sync(0xffffffffu, s, o);
            s2 += __shfl_xor_sync(0xffffffffu, s2, o);
        }
        if (ln == 0) { redA[(grp * 4 + q) * 8 + w] = s; redB[(grp * 4 + q) * 8 + w] = s2; }
    }
    __syncthreads();
    if (t < 8) {
        float s = 0.f, s2 = 0.f;
        #pragma unroll
        for (int k = 0; k < 8; k++) { s += redA[t * 8 + k]; s2 += redB[t * 8 + k]; }
        float m = s * (1.f / 256.f);
        mu[t] = m;
        rs[t] = rsqrtf(s2 * (1.f / 256.f) - m * m + 1e-5f);
    }
    __syncthreads();
    float gg = g[ch], bb = b[ch];
    #pragma unroll
    for (int q = 0; q < 4; q++)
        v[q] = (v[q] - mu[grp * 4 + q]) * rs[grp * 4 + q] * gg + bb;
}

__global__ __launch_bounds__(512) void k_tail(
    const float* __restrict__ vpW, const float* __restrict__ vpb,
    const float* __restrict__ opW, const float* __restrict__ opb,
    const float* __restrict__ g1, const float* __restrict__ b1,
    const float* __restrict__ W1, const float* __restrict__ fb1,
    const float* __restrict__ W2, const float* __restrict__ fb2,
    const float* __restrict__ g2, const float* __restrict__ b2,
    const float* __restrict__ soWn, const float* __restrict__ sobn,
    const float* __restrict__ awWn, const float* __restrict__ awbn,
    int has_next) {
    __shared__ __align__(16) float bufT[256 * TSB];
    __shared__ __align__(16) float qST[256 * TSB];
    __shared__ float redA[8 * 8], redB[8 * 8];
    __shared__ float mu[8], rs[8];
    int t = threadIdx.x;
    int ch = t & 255;
    int grp = t >> 8;
    int qb = grp * 4;
    int qg0 = blockIdx.x * 8;
    int h = ch >> 5;

    float v[4];

    // ---- vp: f32x2 over the reduction dim ----
    {
        ull a2v[4];
        #pragma unroll
        for (int q = 0; q < 4; q++) a2v[q] = pk2(0.f, 0.f);
        for (int i4 = 0; i4 < 64; i4++) {
            float w0 = vpW[(4 * i4 + 0) * CHN + ch];
            float w1 = vpW[(4 * i4 + 1) * CHN + ch];
            float w2 = vpW[(4 * i4 + 2) * CHN + ch];
            float w3 = vpW[(4 * i4 + 3) * CHN + ch];
            ull w01 = pk2(w0, w1), w23 = pk2(w2, w3);
            #pragma unroll
            for (int q = 0; q < 4; q++) {
                const ulonglong2 a = *(const ulonglong2*)&g_agg[((size_t)(qg0 + qb + q) * 8 + h) * CHN + 4 * i4];
                a2v[q] = fma2(a.x, w01, a2v[q]);
                a2v[q] = fma2(a.y, w23, a2v[q]);
            }
        }
        float vb = vpb[ch];
        float4 o;
        float lo, hi;
        upk2(a2v[0], lo, hi); o.x = lo + hi + g_bw[(qg0 + qb + 0) * 8 + h] * vb;
        upk2(a2v[1], lo, hi); o.y = lo + hi + g_bw[(qg0 + qb + 1) * 8 + h] * vb;
        upk2(a2v[2], lo, hi); o.z = lo + hi + g_bw[(qg0 + qb + 2) * 8 + h] * vb;
        upk2(a2v[3], lo, hi); o.w = lo + hi + g_bw[(qg0 + qb + 3) * 8 + h] * vb;
        *(float4*)&bufT[ch * TSB + qb] = o;
    }
    __syncthreads();

    // ---- op ----
    ull acc2[2];
    acc2[0] = pk2(g_q[(qg0 + qb + 0) * CHN + ch], g_q[(qg0 + qb + 1) * CHN + ch]);
    acc2[1] = pk2(g_q[(qg0 + qb + 2) * CHN + ch], g_q[(qg0 + qb + 3) * CHN + ch]);
    #pragma unroll 4
    for (int i = 0; i < 256; i++) {
        float w = opW[i * CHN + ch];
        ull w2 = pk2(w, w);
        const ulonglong2 A0 = *(const ulonglong2*)&bufT[i * TSB + qb];
        acc2[0] = fma2(A0.x, w2, acc2[0]);
        acc2[1] = fma2(A0.y, w2, acc2[1]);
    }
    {
        float ob = opb[ch];
        upk2(acc2[0], v[0], v[1]);
        upk2(acc2[1], v[2], v[3]);
        #pragma unroll
        for (int q = 0; q < 4; q++) v[q] += ob;
    }

    // ---- LN1 ----
    ln4h(v, redA, redB, mu, rs, g1, b1, ch, grp, t);
    *(float4*)&qST[ch * TSB + qb] = make_float4(v[0], v[1], v[2], v[3]);
    __syncthreads();

    // ---- FFN ----
    ull o2[2];
    o2[0] = pk2(0.f, 0.f); o2[1] = pk2(0.f, 0.f);
    for (int chunk = 0; chunk < 4; chunk++) {
        ull h2[2];
        h2[0] = pk2(0.f, 0.f); h2[1] = pk2(0.f, 0.f);
        int j = chunk * CHN + ch;
        #pragma unroll 4
        for (int i = 0; i < 256; i++) {
            float w = W1[i * 1024 + j];
            ull w2 = pk2(w, w);
            const ulonglong2 A0 = *(const ulonglong2*)&qST[i * TSB + qb];
            h2[0] = fma2(A0.x, w2, h2[0]);
            h2[1] = fma2(A0.y, w2, h2[1]);
        }
        float bj = fb1[j];
        {
            float a, b_, c, d_;
            upk2(h2[0], a, b_);
            upk2(h2[1], c, d_);
            *(float4*)&bufT[ch * TSB + qb] = make_float4(
                fmaxf(a + bj, 0.f), fmaxf(b_ + bj, 0.f),
                fmaxf(c + bj, 0.f), fmaxf(d_ + bj, 0.f));
        }
        __syncthreads();
        #pragma unroll 4
        for (int i = 0; i < 256; i++) {
            float w = W2[(chunk * CHN + i) * CHN + ch];
            ull w2 = pk2(w, w);
            const ulonglong2 A0 = *(const ulonglong2*)&bufT[i * TSB + qb];
            o2[0] = fma2(A0.x, w2, o2[0]);
            o2[1] = fma2(A0.y, w2, o2[1]);
        }
        __syncthreads();
    }
    {
        float fb = fb2[ch];
        upk2(o2[0], v[0], v[1]);
        upk2(o2[1], v[2], v[3]);
        #pragma unroll
        for (int q = 0; q < 4; q++) v[q] += qST[ch * TSB + qb + q] + fb;
    }

    // ---- LN2 ----
    ln4h(v, redA, redB, mu, rs, g2, b2, ch, grp, t);
    #pragma unroll
    for (int q = 0; q < 4; q++) g_q[(qg0 + qb + q) * CHN + ch] = v[q];

    // ---- fused next-layer so/aw ----
    if (has_next) {
        #pragma unroll
        for (int q = 0; q < 4; q++)
            bufT[ch * TSB + qb + q] = v[q] + g_qpos[(qg0 + qb + q) * CHN + ch];
        __syncthreads();

        if (t < 256) {
            ull s2[4];
            #pragma unroll
            for (int p = 0; p < 4; p++) s2[p] = pk2(0.f, 0.f);
            #pragma unroll 4
            for (int i = 0; i < 256; i++) {
                float w = soWn[i * CHN + t];
                ull w2 = pk2(w, w);
                const ulonglong2 A0 = *(const ulonglong2*)&bufT[i * TSB + 0];
                const ulonglong2 A1 = *(const ulonglong2*)&bufT[i * TSB + 4];
                s2[0] = fma2(A0.x, w2, s2[0]);
                s2[1] = fma2(A0.y, w2, s2[1]);
                s2[2] = fma2(A1.x, w2, s2[2]);
                s2[3] = fma2(A1.y, w2, s2[3]);
            }
            float sbv = sobn[t];
            #pragma unroll
            for (int p = 0; p < 4; p++) {
                float lo, hi;
                upk2(s2[p], lo, hi);
                g_so[(qg0 + 2 * p) * CHN + t]     = lo + sbv;
                g_so[(qg0 + 2 * p + 1) * CHN + t] = hi + sbv;
            }
        } else if (t < 384) {
            int c = t - 256;
            ull s2[4];
            #pragma unroll
            for (int p = 0; p < 4; p++) s2[p] = pk2(0.f, 0.f);
            #pragma unroll 4
            for (int i = 0; i < 256; i++) {
                float w = awWn[i * 128 + c];
                ull w2 = pk2(w, w);
                const ulonglong2 A0 = *(const ulonglong2*)&bufT[i * TSB + 0];
                const ulonglong2 A1 = *(const ulonglong2*)&bufT[i * TSB + 4];
                s2[0] = fma2(A0.x, w2, s2[0]);
                s2[1] = fma2(A0.y, w2, s2[1]);
                s2[2] = fma2(A1.x, w2, s2[2]);
                s2[3] = fma2(A1.y, w2, s2[3]);
            }
            float ab = awbn[c];
            float av[8];
            #pragma unroll
            for (int p = 0; p < 4; p++) {
                upk2(s2[p], av[2 * p], av[2 * p + 1]);
                av[2 * p] += ab; av[2 * p + 1] += ab;
            }
            #pragma unroll
            for (int q = 0; q < 8; q++) {
                float vv = av[q];
                float m = vv;
                #pragma unroll
                for (int o = 8; o > 0; o >>= 1)
                    m = fmaxf(m, __shfl_xor_sync(0xffffffffu, m, o, 16));
                float e = expf(vv - m);
                float s = e;
                #pragma unroll
                for (int o = 8; o > 0; o >>= 1)
                    s += __shfl_xor_sync(0xffffffffu, s, o, 16);
                g_aw[(qg0 + q) * 128 + c] = e / s;
            }
        }
    }
}

// ---------------- K7/K8: zero-fill output, scatter queries ----------------
__global__ void k_zero(float4* __restrict__ out) {
    out[(size_t)blockIdx.x * 256 + threadIdx.x] = make_float4(0.f, 0.f, 0.f, 0.f);
}

__global__ void k_scatter(float* __restrict__ out) {
    int k = blockIdx.x, t = threadIdx.x;
    int b = k >> 10;
    int ind = g_ind[k];
    out[(b * CHN + t) * HWSZ + ind] = g_q[k * CHN + t];
}

// ---------------- launch (single stream) ----------------
extern "C" void kernel_launch(void* const* d_in, const int* in_sizes, int n_in,
                              void* d_out, int out_size) {
    const float* x    = (const float*)d_in[0];
    const float* preds= (const float*)d_in[1];
    const float* hm   = (const float*)d_in[2];
    const float* mW1  = (const float*)d_in[3];
    const float* mb1  = (const float*)d_in[4];
    const float* mW2  = (const float*)d_in[5];
    const float* mb2  = (const float*)d_in[6];
    const float* tp   = (const float*)d_in[7];
    const float* rowe = (const float*)d_in[8];
    const float* cole = (const float*)d_in[9];
    const float* soW  = (const float*)d_in[10];
    const float* sob  = (const float*)d_in[11];
    const float* awW  = (const float*)d_in[12];
    const float* awb  = (const float*)d_in[13];
    const float* vpW  = (const float*)d_in[14];
    const float* vpb  = (const float*)d_in[15];
    const float* opW  = (const float*)d_in[16];
    const float* opb  = (const float*)d_in[17];
    const float* l1g  = (const float*)d_in[18];
    const float* l1b  = (const float*)d_in[19];
    const float* fW1  = (const float*)d_in[20];
    const float* fb1  = (const float*)d_in[21];
    const float* fW2  = (const float*)d_in[22];
    const float* fb2  = (const float*)d_in[23];
    const float* l2g  = (const float*)d_in[24];
    const float* l2b  = (const float*)d_in[25];
    float* out = (float*)d_out;

    k_transpose<<<dim3(4, 8, 1024), 256>>>(x, tp);
    k_score<<<32, 1024>>>(hm);
    k_topk<<<2, 1024>>>();
    k_qinit<<<1024, 256>>>(preds, mW1, mb1, mW2, mb2, rowe, cole);
    k_soaw<<<256, 384>>>(soW, sob, awW, awb);
    for (int l = 0; l < 3; l++) {
        int nl = l + 1;
        k_gather<<<2048, 256>>>();
        k_tail<<<256, 512>>>(vpW + l * 65536, vpb + l * 256,
                             opW + l * 65536, opb + l * 256,
                             l1g + l * 256, l1b + l * 256,
                             fW1 + l * 262144, fb1 + l * 1024,
                             fW2 + l * 262144, fb2 + l * 256,
                             l2g + l * 256, l2b + l * 256,
                             soW + nl * 65536, sob + nl * 256,
                             awW + nl * 32768, awb + nl * 128,
                             (l < 2) ? 1 : 0);
    }
    k_zero<<<8192, 256>>>((float4*)out);
    k_scatter<<<2048, 256>>>(out);
}